// round 7
// baseline (speedup 1.0000x reference)
#include <cuda_runtime.h>
#include <math.h>

#define NC 128          // hidden / input dim
#define N_MAX 50000
#define E_MAX 800000
#define NG 64
#define SCAN_EPT 16                       // elems per thread in scan
#define SCAN_CHUNK (256 * SCAN_EPT)       // 4096 elems per block

// ---- scratch (static device globals; no allocation allowed) ----
__device__ float g_h[(size_t)N_MAX * NC];
__device__ float g_agg[(size_t)N_MAX * NC];
__device__ float g_asrc[N_MAX];
__device__ float g_adst[N_MAX];
__device__ float g_pool[NG * NC];
__device__ float g_cnt[NG];
__device__ float g_wdst1[NC];
__device__ float g_wdst2[NC];
// normalized int32 graph structure
__device__ int g_src[E_MAX];
__device__ int g_dst[E_MAX];
__device__ int g_batch[N_MAX];
__device__ int g_is64;
// CSR scratch (g_csr holds SRC node ids grouped by dst)
__device__ int g_deg[N_MAX];
__device__ int g_rowstart[N_MAX];
__device__ int g_cursor[N_MAX];
__device__ int g_csr[E_MAX];
__device__ int g_tsum[(N_MAX + SCAN_CHUNK - 1) / SCAN_CHUNK * 256 + 256];

// K0: zero deg/pool, fold W_dst @ att_dst into per-layer 128-vectors.
__global__ void prep_kernel(const float* __restrict__ Wd1, const float* __restrict__ ad1,
                            const float* __restrict__ Wd2, const float* __restrict__ ad2,
                            int n) {
    int t = blockIdx.x * blockDim.x + threadIdx.x;
    if (blockIdx.x == 0) {
        int lt = threadIdx.x;  // 256 threads in block 0
        if (lt < NC) {
            float s = 0.f;
            #pragma unroll 4
            for (int c = 0; c < NC; c++) s += Wd1[lt * NC + c] * ad1[c];
            g_wdst1[lt] = s;
        } else {
            int k = lt - NC;
            float s = 0.f;
            #pragma unroll 4
            for (int c = 0; c < NC; c++) s += Wd2[k * NC + c] * ad2[c];
            g_wdst2[k] = s;
        }
        for (int i = lt; i < NG * NC; i += 256) g_pool[i] = 0.f;
        if (lt < NG) g_cnt[lt] = 0.f;
    }
    if (t < n) g_deg[t] = 0;
}

// K1: detect int64 vs int32 edge_index (JAX x64-off silently emits int32).
__global__ void detect_kernel(const int* __restrict__ ei_words, int E) {
    __shared__ int s_or;
    if (threadIdx.x == 0) s_or = 0;
    __syncthreads();
    int cnt = (E < 2048) ? E : 2048;
    int acc = 0;
    for (int i = threadIdx.x; i < cnt; i += 256) acc |= ei_words[2 * i + 1];
    atomicOr(&s_or, acc);
    __syncthreads();
    if (threadIdx.x == 0) g_is64 = (s_or == 0) ? 1 : 0;
}

// K2: normalize edge_index + batch to int32 AND histogram dst degrees.
__global__ void convert_hist_kernel(const void* __restrict__ ei, const void* __restrict__ batch,
                                    int E, int n) {
    int i = blockIdx.x * blockDim.x + threadIdx.x;
    int is64 = g_is64;
    if (i < E) {
        int s, d;
        if (is64) {
            s = (int)((const long long*)ei)[i];
            d = (int)((const long long*)ei)[E + i];
        } else {
            s = ((const int*)ei)[i];
            d = ((const int*)ei)[E + i];
        }
        g_src[i] = s;
        g_dst[i] = d;
        atomicAdd(&g_deg[d], 1);
    }
    if (i < n) {
        g_batch[i] = is64 ? (int)((const long long*)batch)[i] : ((const int*)batch)[i];
    }
}

// K3a: per-thread partial sums of 16 degrees each (multi-block, full chip).
__global__ void scan_phase1(int n) {
    int tid = blockIdx.x * blockDim.x + threadIdx.x;
    int base = tid * SCAN_EPT;
    int s = 0;
    #pragma unroll
    for (int i = 0; i < SCAN_EPT; i++) {
        int idx = base + i;
        if (idx < n) s += g_deg[idx];
    }
    g_tsum[tid] = s;
}

// K3b: single-block exclusive scan of the thread-partials (all in SMEM).
__global__ void scan_phase2(int total) {
    __shared__ int sS[1024];
    int t = threadIdx.x;
    int per = (total + 1023) / 1024;
    int lo = t * per;
    int hi = lo + per; if (hi > total) hi = total;
    int s = 0;
    for (int i = lo; i < hi; i++) s += g_tsum[i];
    sS[t] = s;
    __syncthreads();
    for (int off = 1; off < 1024; off <<= 1) {
        int v = (t >= off) ? sS[t - off] : 0;
        __syncthreads();
        sS[t] += v;
        __syncthreads();
    }
    int base = (t == 0) ? 0 : sS[t - 1];
    for (int i = lo; i < hi; i++) {
        int v = g_tsum[i];
        g_tsum[i] = base;
        base += v;
    }
}

// K3c: each thread writes rowstart/cursor for its 16 nodes from its offset.
__global__ void scan_phase3(int n) {
    int tid = blockIdx.x * blockDim.x + threadIdx.x;
    int base = g_tsum[tid];
    int start = tid * SCAN_EPT;
    #pragma unroll
    for (int i = 0; i < SCAN_EPT; i++) {
        int idx = start + i;
        if (idx < n) {
            g_rowstart[idx] = base;
            g_cursor[idx]   = base;
            base += g_deg[idx];
        }
    }
}

// K4: scatter SRC node ids into CSR grouped by dst.
__global__ void fill_kernel(int E) {
    int e = blockIdx.x * blockDim.x + threadIdx.x;
    if (e < E) {
        int slot = atomicAdd(&g_cursor[g_dst[e]], 1);
        g_csr[slot] = g_src[e];
    }
}

// K5: fused node GEMM. 256 threads/block, 32 rows/block, warp handles 4 rows.
// layer==0: X = X_ext.  layer==1: X = relu(g_agg + bias_in).
// Writes g_h = X@W, g_asrc = h@att, g_adst = X@wdst_layer.
__global__ void node_gemm(const float* __restrict__ X_ext, const float* __restrict__ bias_in,
                          const float* __restrict__ W, const float* __restrict__ att,
                          int layer, int n) {
    __shared__ __align__(16) float sX[32 * NC];
    __shared__ __align__(16) float sAtt[NC];
    __shared__ __align__(16) float sW[NC];
    int t = threadIdx.x;
    int row0 = blockIdx.x * 32;
    const float* wdst = (layer == 0) ? g_wdst1 : g_wdst2;
    const float* X    = (layer == 0) ? X_ext : g_agg;
    if (t < NC) sAtt[t] = att[t];
    else        sW[t - NC] = wdst[t - NC];

    for (int i = t; i < 32 * NC; i += 256) {
        int r = i >> 7, c = i & (NC - 1);
        int gr = row0 + r;
        float v = 0.f;
        if (gr < n) {
            v = X[(size_t)gr * NC + c];
            if (layer == 1) v = fmaxf(v + bias_in[c], 0.f);
        }
        sX[i] = v;
    }
    __syncthreads();

    int warp = t >> 5, lane = t & 31;
    const float4* xr4 = (const float4*)&sX[warp * 4 * NC];
    float4 acc[4];
    #pragma unroll
    for (int r = 0; r < 4; r++) acc[r] = make_float4(0.f, 0.f, 0.f, 0.f);

    const float4* W4 = (const float4*)W;
    #pragma unroll 2
    for (int k4 = 0; k4 < NC / 4; k4++) {
        float4 x0 = xr4[k4];
        float4 x1 = xr4[32 + k4];
        float4 x2 = xr4[64 + k4];
        float4 x3 = xr4[96 + k4];
        #pragma unroll
        for (int kk = 0; kk < 4; kk++) {
            float4 w = __ldg(&W4[(k4 * 4 + kk) * 32 + lane]);
            float e0 = (&x0.x)[kk], e1 = (&x1.x)[kk], e2 = (&x2.x)[kk], e3 = (&x3.x)[kk];
            acc[0].x += e0 * w.x; acc[0].y += e0 * w.y; acc[0].z += e0 * w.z; acc[0].w += e0 * w.w;
            acc[1].x += e1 * w.x; acc[1].y += e1 * w.y; acc[1].z += e1 * w.z; acc[1].w += e1 * w.w;
            acc[2].x += e2 * w.x; acc[2].y += e2 * w.y; acc[2].z += e2 * w.z; acc[2].w += e2 * w.w;
            acc[3].x += e3 * w.x; acc[3].y += e3 * w.y; acc[3].z += e3 * w.z; acc[3].w += e3 * w.w;
        }
    }

    float4 attv = *(const float4*)&sAtt[lane * 4];
    float4 wv   = *(const float4*)&sW[lane * 4];
    const float* xr = &sX[warp * 4 * NC];
    #pragma unroll
    for (int r = 0; r < 4; r++) {
        int gr = row0 + warp * 4 + r;
        if (gr < n) {
            float4 a = acc[r];
            *(float4*)&g_h[(size_t)gr * NC + lane * 4] = a;
            float pa = a.x * attv.x + a.y * attv.y + a.z * attv.z + a.w * attv.w;
            const float* xrow = xr + r * NC;
            float pd = xrow[lane * 4 + 0] * wv.x + xrow[lane * 4 + 1] * wv.y +
                       xrow[lane * 4 + 2] * wv.z + xrow[lane * 4 + 3] * wv.w;
            #pragma unroll
            for (int o = 16; o > 0; o >>= 1) {
                pa += __shfl_xor_sync(0xffffffffu, pa, o);
                pd += __shfl_xor_sync(0xffffffffu, pd, o);
            }
            if (lane == 0) { g_asrc[gr] = pa; g_adst[gr] = pd; }
        }
    }
}

// K6: single-pass fused softmax + CSR aggregation, warp per dst node.
// out = (sum_e p_e * h[src_e]) / (sum_e p_e + 1e-16)  — normalization is
// distributive, so no separate denominator pass is needed.
__global__ void aggregate_fused(const float* __restrict__ bias2, int layer, int n) {
    int node = (blockIdx.x * blockDim.x + threadIdx.x) >> 5;
    int lane = threadIdx.x & 31;
    if (node >= n) return;
    int start = g_rowstart[node];
    int cnt   = g_deg[node];
    float adst = g_adst[node];

    float dsum = 0.f;
    float4 acc = make_float4(0.f, 0.f, 0.f, 0.f);

    for (int j0 = 0; j0 < cnt; j0 += 32) {
        int j = j0 + lane;
        int sN = 0; float w = 0.f;
        if (j < cnt) {
            sN = g_csr[start + j];
            float v = g_asrc[sN] + adst;
            v = (v >= 0.f) ? v : 0.2f * v;
            w = __expf(v);
        }
        dsum += w;
        int m = cnt - j0; if (m > 32) m = 32;
        int k = 0;
        // 4x unrolled gather: 4 outstanding 512B loads per warp iteration
        for (; k + 4 <= m; k += 4) {
            int   s0 = __shfl_sync(0xffffffffu, sN, k + 0);
            int   s1 = __shfl_sync(0xffffffffu, sN, k + 1);
            int   s2 = __shfl_sync(0xffffffffu, sN, k + 2);
            int   s3 = __shfl_sync(0xffffffffu, sN, k + 3);
            float w0 = __shfl_sync(0xffffffffu, w, k + 0);
            float w1 = __shfl_sync(0xffffffffu, w, k + 1);
            float w2 = __shfl_sync(0xffffffffu, w, k + 2);
            float w3 = __shfl_sync(0xffffffffu, w, k + 3);
            float4 h0 = *(const float4*)&g_h[(size_t)s0 * NC + lane * 4];
            float4 h1 = *(const float4*)&g_h[(size_t)s1 * NC + lane * 4];
            float4 h2 = *(const float4*)&g_h[(size_t)s2 * NC + lane * 4];
            float4 h3 = *(const float4*)&g_h[(size_t)s3 * NC + lane * 4];
            acc.x += w0 * h0.x; acc.y += w0 * h0.y; acc.z += w0 * h0.z; acc.w += w0 * h0.w;
            acc.x += w1 * h1.x; acc.y += w1 * h1.y; acc.z += w1 * h1.z; acc.w += w1 * h1.w;
            acc.x += w2 * h2.x; acc.y += w2 * h2.y; acc.z += w2 * h2.z; acc.w += w2 * h2.w;
            acc.x += w3 * h3.x; acc.y += w3 * h3.y; acc.z += w3 * h3.z; acc.w += w3 * h3.w;
        }
        for (; k < m; k++) {
            int   sk = __shfl_sync(0xffffffffu, sN, k);
            float wk = __shfl_sync(0xffffffffu, w, k);
            float4 h = *(const float4*)&g_h[(size_t)sk * NC + lane * 4];
            acc.x += wk * h.x; acc.y += wk * h.y; acc.z += wk * h.z; acc.w += wk * h.w;
        }
    }

    #pragma unroll
    for (int o = 16; o > 0; o >>= 1) dsum += __shfl_xor_sync(0xffffffffu, dsum, o);
    float inv = 1.f / (dsum + 1e-16f);
    acc.x *= inv; acc.y *= inv; acc.z *= inv; acc.w *= inv;

    if (layer == 0) {
        *(float4*)&g_agg[(size_t)node * NC + lane * 4] = acc;
    } else {
        int g = g_batch[node];
        float b0 = bias2[lane * 4 + 0], b1 = bias2[lane * 4 + 1];
        float b2 = bias2[lane * 4 + 2], b3 = bias2[lane * 4 + 3];
        float* dstp = &g_pool[g * NC + lane * 4];
        atomicAdd(dstp + 0, fmaxf(acc.x + b0, 0.f));
        atomicAdd(dstp + 1, fmaxf(acc.y + b1, 0.f));
        atomicAdd(dstp + 2, fmaxf(acc.z + b2, 0.f));
        atomicAdd(dstp + 3, fmaxf(acc.w + b3, 0.f));
        if (lane == 0) atomicAdd(&g_cnt[g], 1.0f);
    }
}

// K7: out = (pool/cnt) @ W_lin + b_lin  (64 x 128)
__global__ void final_linear(const float* __restrict__ Wl, const float* __restrict__ bl,
                             float* __restrict__ out) {
    __shared__ __align__(16) float sP[NC];
    int g = blockIdx.x, c = threadIdx.x;
    sP[c] = g_pool[g * NC + c] / fmaxf(g_cnt[g], 1.0f);
    __syncthreads();
    float acc = bl[c];
    #pragma unroll 4
    for (int k = 0; k < NC; k++) acc += sP[k] * Wl[k * NC + c];
    out[g * NC + c] = acc;
}

extern "C" void kernel_launch(void* const* d_in, const int* in_sizes, int n_in,
                              void* d_out, int out_size) {
    const float* x     = (const float*)d_in[0];
    const void*  ei    = d_in[1];
    const void*  batch = d_in[2];
    const float* Wsrc1   = (const float*)d_in[3];
    const float* Wdst1   = (const float*)d_in[4];
    const float* attsrc1 = (const float*)d_in[5];
    const float* attdst1 = (const float*)d_in[6];
    const float* bias1   = (const float*)d_in[7];
    const float* Wsrc2   = (const float*)d_in[8];
    const float* Wdst2   = (const float*)d_in[9];
    const float* attsrc2 = (const float*)d_in[10];
    const float* attdst2 = (const float*)d_in[11];
    const float* bias2   = (const float*)d_in[12];
    const float* Wlin    = (const float*)d_in[13];
    const float* blin    = (const float*)d_in[14];

    int n = in_sizes[0] / NC;
    int E = in_sizes[1] / 2;

    int gemm_blocks = (n + 31) / 32;
    int e_blocks    = (E + 255) / 256;
    int warp_blocks = (n + 7) / 8;
    int prep_blocks = (n + 255) / 256;
    int conv_blocks = ((E > n ? E : n) + 255) / 256;
    int scan_blocks = (n + SCAN_CHUNK - 1) / SCAN_CHUNK;
    int scan_total  = scan_blocks * 256;

    prep_kernel<<<prep_blocks, 256>>>(Wdst1, attdst1, Wdst2, attdst2, n);
    detect_kernel<<<1, 256>>>((const int*)ei, E);
    convert_hist_kernel<<<conv_blocks, 256>>>(ei, batch, E, n);

    // Layer-1 GEMM has no CSR dependency — placed 4th so ncu's window shows it.
    node_gemm<<<gemm_blocks, 256>>>(x, nullptr, Wsrc1, attsrc1, 0, n);

    scan_phase1<<<scan_blocks, 256>>>(n);
    scan_phase2<<<1, 1024>>>(scan_total);
    scan_phase3<<<scan_blocks, 256>>>(n);
    fill_kernel<<<e_blocks, 256>>>(E);

    aggregate_fused<<<warp_blocks, 256>>>(nullptr, 0, n);

    // Layer 2
    node_gemm<<<gemm_blocks, 256>>>(nullptr, bias1, Wsrc2, attsrc2, 1, n);
    aggregate_fused<<<warp_blocks, 256>>>(bias2, 1, n);

    // Head
    final_linear<<<NG, NC>>>(Wlin, blin, (float*)d_out);
}

// round 8
// speedup vs baseline: 1.0734x; 1.0734x over previous
#include <cuda_runtime.h>
#include <cuda_fp16.h>
#include <math.h>

#define NC 128          // hidden / input dim
#define N_MAX 50000
#define E_MAX 800000
#define NG 64
#define SCAN_EPT 16
#define SCAN_CHUNK (256 * SCAN_EPT)

// ---- scratch (static device globals; no allocation allowed) ----
__device__ __half g_h16[(size_t)N_MAX * NC];   // h in fp16 (gather payload only)
__device__ float g_agg[(size_t)N_MAX * NC];
__device__ float g_asrc[N_MAX];
__device__ float g_adst[N_MAX];
__device__ float g_pool[NG * NC];
__device__ float g_cnt[NG];
__device__ float g_wdst1[NC];
__device__ float g_wdst2[NC];
// normalized int32 graph structure
__device__ int g_src[E_MAX];
__device__ int g_dst[E_MAX];
__device__ int g_batch[N_MAX];
__device__ int g_is64;
// CSR scratch (g_csr holds SRC node ids grouped by dst)
__device__ int g_deg[N_MAX];
__device__ int g_rowstart[N_MAX];
__device__ int g_cursor[N_MAX];
__device__ int g_csr[E_MAX];
__device__ int g_tsum[(N_MAX + SCAN_CHUNK - 1) / SCAN_CHUNK * 256 + 256];

// K0: zero deg/pool, fold W_dst @ att_dst into per-layer 128-vectors.
__global__ void prep_kernel(const float* __restrict__ Wd1, const float* __restrict__ ad1,
                            const float* __restrict__ Wd2, const float* __restrict__ ad2,
                            int n) {
    int t = blockIdx.x * blockDim.x + threadIdx.x;
    if (blockIdx.x == 0) {
        int lt = threadIdx.x;
        if (lt < NC) {
            float s = 0.f;
            #pragma unroll 4
            for (int c = 0; c < NC; c++) s += Wd1[lt * NC + c] * ad1[c];
            g_wdst1[lt] = s;
        } else {
            int k = lt - NC;
            float s = 0.f;
            #pragma unroll 4
            for (int c = 0; c < NC; c++) s += Wd2[k * NC + c] * ad2[c];
            g_wdst2[k] = s;
        }
        for (int i = lt; i < NG * NC; i += 256) g_pool[i] = 0.f;
        if (lt < NG) g_cnt[lt] = 0.f;
    }
    if (t < n) g_deg[t] = 0;
}

// K1: detect int64 vs int32 edge_index (JAX x64-off silently emits int32).
__global__ void detect_kernel(const int* __restrict__ ei_words, int E) {
    __shared__ int s_or;
    if (threadIdx.x == 0) s_or = 0;
    __syncthreads();
    int cnt = (E < 2048) ? E : 2048;
    int acc = 0;
    for (int i = threadIdx.x; i < cnt; i += 256) acc |= ei_words[2 * i + 1];
    atomicOr(&s_or, acc);
    __syncthreads();
    if (threadIdx.x == 0) g_is64 = (s_or == 0) ? 1 : 0;
}

// K2: normalize edge_index + batch to int32 AND histogram dst degrees.
__global__ void convert_hist_kernel(const void* __restrict__ ei, const void* __restrict__ batch,
                                    int E, int n) {
    int i = blockIdx.x * blockDim.x + threadIdx.x;
    int is64 = g_is64;
    if (i < E) {
        int s, d;
        if (is64) {
            s = (int)((const long long*)ei)[i];
            d = (int)((const long long*)ei)[E + i];
        } else {
            s = ((const int*)ei)[i];
            d = ((const int*)ei)[E + i];
        }
        g_src[i] = s;
        g_dst[i] = d;
        atomicAdd(&g_deg[d], 1);
    }
    if (i < n) {
        g_batch[i] = is64 ? (int)((const long long*)batch)[i] : ((const int*)batch)[i];
    }
}

// K3a/b/c: multi-block exclusive scan of degrees.
__global__ void scan_phase1(int n) {
    int tid = blockIdx.x * blockDim.x + threadIdx.x;
    int base = tid * SCAN_EPT;
    int s = 0;
    #pragma unroll
    for (int i = 0; i < SCAN_EPT; i++) {
        int idx = base + i;
        if (idx < n) s += g_deg[idx];
    }
    g_tsum[tid] = s;
}

__global__ void scan_phase2(int total) {
    __shared__ int sS[1024];
    int t = threadIdx.x;
    int per = (total + 1023) / 1024;
    int lo = t * per;
    int hi = lo + per; if (hi > total) hi = total;
    int s = 0;
    for (int i = lo; i < hi; i++) s += g_tsum[i];
    sS[t] = s;
    __syncthreads();
    for (int off = 1; off < 1024; off <<= 1) {
        int v = (t >= off) ? sS[t - off] : 0;
        __syncthreads();
        sS[t] += v;
        __syncthreads();
    }
    int base = (t == 0) ? 0 : sS[t - 1];
    for (int i = lo; i < hi; i++) {
        int v = g_tsum[i];
        g_tsum[i] = base;
        base += v;
    }
}

__global__ void scan_phase3(int n) {
    int tid = blockIdx.x * blockDim.x + threadIdx.x;
    int base = g_tsum[tid];
    int start = tid * SCAN_EPT;
    #pragma unroll
    for (int i = 0; i < SCAN_EPT; i++) {
        int idx = start + i;
        if (idx < n) {
            g_rowstart[idx] = base;
            g_cursor[idx]   = base;
            base += g_deg[idx];
        }
    }
}

// K4: scatter SRC node ids into CSR grouped by dst.
__global__ void fill_kernel(int E) {
    int e = blockIdx.x * blockDim.x + threadIdx.x;
    if (e < E) {
        int slot = atomicAdd(&g_cursor[g_dst[e]], 1);
        g_csr[slot] = g_src[e];
    }
}

// K5: node GEMM v2. 256 threads/block, 64 rows/block, warp handles 8 rows.
// layer==0: X = X_ext.  layer==1: X = relu(g_agg + bias_in).
// Writes g_h16 = fp16(X@W), g_asrc = h@att, g_adst = X@wdst_layer.
__global__ void __launch_bounds__(256) node_gemm(
        const float* __restrict__ X_ext, const float* __restrict__ bias_in,
        const float* __restrict__ W, const float* __restrict__ att,
        int layer, int n) {
    __shared__ __align__(16) float sX[64 * NC];
    __shared__ __align__(16) float sAtt[NC];
    __shared__ __align__(16) float sW[NC];
    int t = threadIdx.x;
    int row0 = blockIdx.x * 64;
    const float* wdst = (layer == 0) ? g_wdst1 : g_wdst2;
    const float* X    = (layer == 0) ? X_ext : g_agg;
    if (t < NC) sAtt[t] = att[t];
    else        sW[t - NC] = wdst[t - NC];

    // load 64 rows as float4, relu(x+bias) for layer 1
    float4* sX4 = (float4*)sX;
    const float4* X4 = (const float4*)X;
    const float4* B4 = (const float4*)bias_in;
    #pragma unroll
    for (int i = 0; i < 8; i++) {
        int j = i * 256 + t;          // 0..2047
        int r = j >> 5, c4 = j & 31;
        int gr = row0 + r;
        float4 v = make_float4(0.f, 0.f, 0.f, 0.f);
        if (gr < n) {
            v = X4[(size_t)gr * 32 + c4];
            if (layer == 1) {
                float4 b = B4[c4];
                v.x = fmaxf(v.x + b.x, 0.f);
                v.y = fmaxf(v.y + b.y, 0.f);
                v.z = fmaxf(v.z + b.z, 0.f);
                v.w = fmaxf(v.w + b.w, 0.f);
            }
        }
        sX4[j] = v;
    }
    __syncthreads();

    int warp = t >> 5, lane = t & 31;
    const float4* xr4 = (const float4*)&sX[warp * 8 * NC];   // 8 rows x 32 float4
    float4 acc[8];
    #pragma unroll
    for (int r = 0; r < 8; r++) acc[r] = make_float4(0.f, 0.f, 0.f, 0.f);

    const float4* W4 = (const float4*)W;
    for (int k4 = 0; k4 < NC / 4; k4++) {
        float4 xv[8];
        #pragma unroll
        for (int r = 0; r < 8; r++) xv[r] = xr4[r * 32 + k4];
        #pragma unroll
        for (int kk = 0; kk < 4; kk++) {
            float4 w = __ldg(&W4[(k4 * 4 + kk) * 32 + lane]);
            #pragma unroll
            for (int r = 0; r < 8; r++) {
                float e = (&xv[r].x)[kk];
                acc[r].x += e * w.x; acc[r].y += e * w.y;
                acc[r].z += e * w.z; acc[r].w += e * w.w;
            }
        }
    }

    float4 attv = *(const float4*)&sAtt[lane * 4];
    float4 wv   = *(const float4*)&sW[lane * 4];
    const float* xr = &sX[warp * 8 * NC];
    #pragma unroll
    for (int r = 0; r < 8; r++) {
        int gr = row0 + warp * 8 + r;
        if (gr < n) {
            float4 a = acc[r];
            // fp16 store (8 bytes per lane; row = 256B)
            union { __half2 h[2]; uint2 u; } cv;
            cv.h[0] = __floats2half2_rn(a.x, a.y);
            cv.h[1] = __floats2half2_rn(a.z, a.w);
            *(uint2*)&g_h16[(size_t)gr * NC + lane * 4] = cv.u;

            float pa = a.x * attv.x + a.y * attv.y + a.z * attv.z + a.w * attv.w;
            const float* xrow = xr + r * NC;
            float pd = xrow[lane * 4 + 0] * wv.x + xrow[lane * 4 + 1] * wv.y +
                       xrow[lane * 4 + 2] * wv.z + xrow[lane * 4 + 3] * wv.w;
            #pragma unroll
            for (int o = 16; o > 0; o >>= 1) {
                pa += __shfl_xor_sync(0xffffffffu, pa, o);
                pd += __shfl_xor_sync(0xffffffffu, pd, o);
            }
            if (lane == 0) { g_asrc[gr] = pa; g_adst[gr] = pd; }
        }
    }
}

// K6: single-pass fused softmax + CSR aggregation (fp16 gather), warp per node.
__global__ void aggregate_fused(const float* __restrict__ bias2, int layer, int n) {
    int node = (blockIdx.x * blockDim.x + threadIdx.x) >> 5;
    int lane = threadIdx.x & 31;
    if (node >= n) return;
    int start = g_rowstart[node];
    int cnt   = g_deg[node];
    float adst = g_adst[node];

    float dsum = 0.f;
    float4 acc = make_float4(0.f, 0.f, 0.f, 0.f);

    for (int j0 = 0; j0 < cnt; j0 += 32) {
        int j = j0 + lane;
        int sN = 0; float w = 0.f;
        if (j < cnt) {
            sN = g_csr[start + j];
            float v = g_asrc[sN] + adst;
            v = (v >= 0.f) ? v : 0.2f * v;
            w = __expf(v);
        }
        dsum += w;
        int m = cnt - j0; if (m > 32) m = 32;
        int k = 0;
        // 8x unrolled fp16 gather: 8 outstanding 256B loads per warp group
        for (; k + 8 <= m; k += 8) {
            int   si[8]; float wi[8]; uint2 raw[8];
            #pragma unroll
            for (int q = 0; q < 8; q++) {
                si[q] = __shfl_sync(0xffffffffu, sN, k + q);
                wi[q] = __shfl_sync(0xffffffffu, w, k + q);
            }
            #pragma unroll
            for (int q = 0; q < 8; q++)
                raw[q] = *(const uint2*)&g_h16[(size_t)si[q] * NC + lane * 4];
            #pragma unroll
            for (int q = 0; q < 8; q++) {
                float2 f0 = __half22float2(*(__half2*)&raw[q].x);
                float2 f1 = __half22float2(*(__half2*)&raw[q].y);
                acc.x += wi[q] * f0.x; acc.y += wi[q] * f0.y;
                acc.z += wi[q] * f1.x; acc.w += wi[q] * f1.y;
            }
        }
        for (; k < m; k++) {
            int   sk = __shfl_sync(0xffffffffu, sN, k);
            float wk = __shfl_sync(0xffffffffu, w, k);
            uint2 raw = *(const uint2*)&g_h16[(size_t)sk * NC + lane * 4];
            float2 f0 = __half22float2(*(__half2*)&raw.x);
            float2 f1 = __half22float2(*(__half2*)&raw.y);
            acc.x += wk * f0.x; acc.y += wk * f0.y;
            acc.z += wk * f1.x; acc.w += wk * f1.y;
        }
    }

    #pragma unroll
    for (int o = 16; o > 0; o >>= 1) dsum += __shfl_xor_sync(0xffffffffu, dsum, o);
    float inv = 1.f / (dsum + 1e-16f);
    acc.x *= inv; acc.y *= inv; acc.z *= inv; acc.w *= inv;

    if (layer == 0) {
        *(float4*)&g_agg[(size_t)node * NC + lane * 4] = acc;
    } else {
        int g = g_batch[node];
        float b0 = bias2[lane * 4 + 0], b1 = bias2[lane * 4 + 1];
        float b2 = bias2[lane * 4 + 2], b3 = bias2[lane * 4 + 3];
        float* dstp = &g_pool[g * NC + lane * 4];
        atomicAdd(dstp + 0, fmaxf(acc.x + b0, 0.f));
        atomicAdd(dstp + 1, fmaxf(acc.y + b1, 0.f));
        atomicAdd(dstp + 2, fmaxf(acc.z + b2, 0.f));
        atomicAdd(dstp + 3, fmaxf(acc.w + b3, 0.f));
        if (lane == 0) atomicAdd(&g_cnt[g], 1.0f);
    }
}

// K7: out = (pool/cnt) @ W_lin + b_lin  (64 x 128)
__global__ void final_linear(const float* __restrict__ Wl, const float* __restrict__ bl,
                             float* __restrict__ out) {
    __shared__ __align__(16) float sP[NC];
    int g = blockIdx.x, c = threadIdx.x;
    sP[c] = g_pool[g * NC + c] / fmaxf(g_cnt[g], 1.0f);
    __syncthreads();
    float acc = bl[c];
    #pragma unroll 4
    for (int k = 0; k < NC; k++) acc += sP[k] * Wl[k * NC + c];
    out[g * NC + c] = acc;
}

extern "C" void kernel_launch(void* const* d_in, const int* in_sizes, int n_in,
                              void* d_out, int out_size) {
    const float* x     = (const float*)d_in[0];
    const void*  ei    = d_in[1];
    const void*  batch = d_in[2];
    const float* Wsrc1   = (const float*)d_in[3];
    const float* Wdst1   = (const float*)d_in[4];
    const float* attsrc1 = (const float*)d_in[5];
    const float* attdst1 = (const float*)d_in[6];
    const float* bias1   = (const float*)d_in[7];
    const float* Wsrc2   = (const float*)d_in[8];
    const float* Wdst2   = (const float*)d_in[9];
    const float* attsrc2 = (const float*)d_in[10];
    const float* attdst2 = (const float*)d_in[11];
    const float* bias2   = (const float*)d_in[12];
    const float* Wlin    = (const float*)d_in[13];
    const float* blin    = (const float*)d_in[14];

    int n = in_sizes[0] / NC;
    int E = in_sizes[1] / 2;

    int gemm_blocks = (n + 63) / 64;
    int e_blocks    = (E + 255) / 256;
    int warp_blocks = (n + 7) / 8;
    int prep_blocks = (n + 255) / 256;
    int conv_blocks = ((E > n ? E : n) + 255) / 256;
    int scan_blocks = (n + SCAN_CHUNK - 1) / SCAN_CHUNK;
    int scan_total  = scan_blocks * 256;

    prep_kernel<<<prep_blocks, 256>>>(Wdst1, attdst1, Wdst2, attdst2, n);
    detect_kernel<<<1, 256>>>((const int*)ei, E);
    convert_hist_kernel<<<conv_blocks, 256>>>(ei, batch, E, n);

    // Layer-1 GEMM in slot 4 (ncu capture window)
    node_gemm<<<gemm_blocks, 256>>>(x, nullptr, Wsrc1, attsrc1, 0, n);

    scan_phase1<<<scan_blocks, 256>>>(n);
    scan_phase2<<<1, 1024>>>(scan_total);
    scan_phase3<<<scan_blocks, 256>>>(n);
    fill_kernel<<<e_blocks, 256>>>(E);

    aggregate_fused<<<warp_blocks, 256>>>(nullptr, 0, n);

    // Layer 2
    node_gemm<<<gemm_blocks, 256>>>(nullptr, bias1, Wsrc2, attsrc2, 1, n);
    aggregate_fused<<<warp_blocks, 256>>>(bias2, 1, n);

    // Head
    final_linear<<<NG, NC>>>(Wlin, blin, (float*)d_out);
}

// round 9
// speedup vs baseline: 1.1035x; 1.0281x over previous
#include <cuda_runtime.h>
#include <cuda_fp16.h>
#include <math.h>

#define NC 128          // hidden / input dim
#define N_MAX 50000
#define E_MAX 800000
#define NG 64
#define PBLK 148        // persistent kernels: 1 block/SM, all resident

// ---- scratch (static device globals; no allocation allowed) ----
__device__ __half g_h16[(size_t)N_MAX * NC];   // h in fp16 (gather payload only)
__device__ float g_agg[(size_t)N_MAX * NC];
__device__ float g_asrc[N_MAX];
__device__ float g_adst[N_MAX];
__device__ float g_pool[NG * NC];
__device__ float g_cnt[NG];
__device__ float g_wdst1[NC];
__device__ float g_wdst2[NC];
__device__ int g_src[E_MAX];
__device__ int g_dst[E_MAX];
__device__ int g_batch[N_MAX];
__device__ int g_deg[N_MAX];
__device__ int g_rowstart[N_MAX];
__device__ int g_cursor[N_MAX];
__device__ int g_csr[E_MAX];
__device__ int g_bsum[PBLK];
// monotonically-increasing grid barrier state (epoch-based; replay-safe)
__device__ unsigned g_bar_cnt;
__device__ unsigned g_bar_rel;

// Grid-wide spin barrier for persistent kernels with ALL blocks resident.
// Epoch counters grow monotonically across barriers AND graph replays.
__device__ __forceinline__ void grid_barrier(unsigned nblocks) {
    __threadfence();
    __syncthreads();
    if (threadIdx.x == 0) {
        unsigned my = atomicAdd(&g_bar_cnt, 1u) + 1u;         // 1-based arrival
        unsigned epoch = (my + nblocks - 1u) / nblocks;       // epoch to wait for
        if (my % nblocks == 0u) atomicAdd(&g_bar_rel, 1u);    // last arriver releases
        while (atomicAdd(&g_bar_rel, 0u) < epoch) __nanosleep(128);
        __threadfence();
    }
    __syncthreads();
}

// ---- packed f32x2 helpers (sm_103a FFMA2 path; ptxas won't emit from C++) ----
__device__ __forceinline__ unsigned long long pk2(float lo, float hi) {
    unsigned long long r;
    asm("mov.b64 %0, {%1, %2};" : "=l"(r) : "f"(lo), "f"(hi));
    return r;
}
__device__ __forceinline__ unsigned long long fma2(unsigned long long a,
                                                   unsigned long long b,
                                                   unsigned long long c) {
    unsigned long long d;
    asm("fma.rn.f32x2 %0, %1, %2, %3;" : "=l"(d) : "l"(a), "l"(b), "l"(c));
    return d;
}
__device__ __forceinline__ float2 upk2(unsigned long long v) {
    float x, y;
    asm("mov.b64 {%0, %1}, %2;" : "=f"(x), "=f"(y) : "l"(v));
    return make_float2(x, y);
}

// K1 (persistent): zero deg/pool/cnt + fold wdst, BARRIER, detect+convert+hist.
__global__ void __launch_bounds__(256) mega_prep(
        const float* __restrict__ Wd1, const float* __restrict__ ad1,
        const float* __restrict__ Wd2, const float* __restrict__ ad2,
        const void* __restrict__ ei, const void* __restrict__ batch,
        int E, int n) {
    int tid = threadIdx.x, b = blockIdx.x;
    int gstep = PBLK * 256;
    int gt = b * 256 + tid;

    // phase A: zero + weight folds
    for (int i = gt; i < n; i += gstep) g_deg[i] = 0;
    if (b == 0) {
        if (tid < NC) {
            float s = 0.f;
            #pragma unroll 4
            for (int c = 0; c < NC; c++) s += Wd1[tid * NC + c] * ad1[c];
            g_wdst1[tid] = s;
        } else {
            int k = tid - NC;
            float s = 0.f;
            #pragma unroll 4
            for (int c = 0; c < NC; c++) s += Wd2[k * NC + c] * ad2[c];
            g_wdst2[k] = s;
        }
    }
    if (b == 1 || PBLK == 1) {
        for (int i = tid; i < NG * NC; i += 256) g_pool[i] = 0.f;
        if (tid < NG) g_cnt[tid] = 0.f;
    }

    // per-block int64 detection (every block computes the same answer)
    __shared__ int s_or;
    if (tid == 0) s_or = 0;
    __syncthreads();
    {
        const int* w = (const int*)ei;
        int cnt = (E < 2048) ? E : 2048;
        int acc = 0;
        for (int i = tid; i < cnt; i += 256) acc |= w[2 * i + 1];
        atomicOr(&s_or, acc);
    }
    __syncthreads();
    int is64 = (s_or == 0) ? 1 : 0;

    grid_barrier(PBLK);   // deg must be zero chip-wide before hist atomics

    // phase B: convert + histogram
    for (int i = gt; i < E; i += gstep) {
        int s, d;
        if (is64) {
            s = (int)((const long long*)ei)[i];
            d = (int)((const long long*)ei)[E + i];
        } else {
            s = ((const int*)ei)[i];
            d = ((const int*)ei)[E + i];
        }
        g_src[i] = s;
        g_dst[i] = d;
        atomicAdd(&g_deg[d], 1);
    }
    for (int i = gt; i < n; i += gstep)
        g_batch[i] = is64 ? (int)((const long long*)batch)[i] : ((const int*)batch)[i];
}

// K3 (persistent): degree scan (block-local + cross-block) then CSR fill.
__global__ void __launch_bounds__(256) scan_fill_kernel(int n, int E) {
    __shared__ int sS[256];
    __shared__ int sBase;
    int tid = threadIdx.x, b = blockIdx.x;
    int C = (n + PBLK - 1) / PBLK;           // nodes per block
    int ept = (C + 255) / 256;               // nodes per thread
    int nb1 = min(n, (b + 1) * C);
    int t0 = b * C + tid * ept;

    int s = 0;
    for (int i = 0; i < ept; i++) {
        int idx = t0 + i;
        if (idx < nb1) s += g_deg[idx];
    }
    sS[tid] = s;
    __syncthreads();
    for (int off = 1; off < 256; off <<= 1) {
        int v = (tid >= off) ? sS[tid - off] : 0;
        __syncthreads();
        sS[tid] += v;
        __syncthreads();
    }
    int excl = sS[tid] - s;
    if (tid == 255) g_bsum[b] = sS[255];

    grid_barrier(PBLK);

    if (tid == 0) {
        int base = 0;
        for (int i = 0; i < b; i++) base += g_bsum[i];
        sBase = base;
    }
    __syncthreads();
    int base = sBase + excl;
    for (int i = 0; i < ept; i++) {
        int idx = t0 + i;
        if (idx < nb1) {
            g_rowstart[idx] = base;
            g_cursor[idx]   = base;
            base += g_deg[idx];
        }
    }

    grid_barrier(PBLK);

    for (int e = b * 256 + tid; e < E; e += PBLK * 256) {
        int slot = atomicAdd(&g_cursor[g_dst[e]], 1);
        g_csr[slot] = g_src[e];
    }
}

// K2/K5: node GEMM with packed f32x2 FMA. 64 rows/block, warp handles 8 rows.
__global__ void __launch_bounds__(256) node_gemm(
        const float* __restrict__ X_ext, const float* __restrict__ bias_in,
        const float* __restrict__ W, const float* __restrict__ att,
        int layer, int n) {
    __shared__ __align__(16) float sX[64 * NC];
    __shared__ __align__(16) float sAtt[NC];
    __shared__ __align__(16) float sW[NC];
    int t = threadIdx.x;
    int row0 = blockIdx.x * 64;
    const float* wdst = (layer == 0) ? g_wdst1 : g_wdst2;
    const float* X    = (layer == 0) ? X_ext : g_agg;
    if (t < NC) sAtt[t] = att[t];
    else        sW[t - NC] = wdst[t - NC];

    float4* sX4 = (float4*)sX;
    const float4* X4 = (const float4*)X;
    const float4* B4 = (const float4*)bias_in;
    #pragma unroll
    for (int i = 0; i < 8; i++) {
        int j = i * 256 + t;
        int r = j >> 5, c4 = j & 31;
        int gr = row0 + r;
        float4 v = make_float4(0.f, 0.f, 0.f, 0.f);
        if (gr < n) {
            v = X4[(size_t)gr * 32 + c4];
            if (layer == 1) {
                float4 bb = B4[c4];
                v.x = fmaxf(v.x + bb.x, 0.f);
                v.y = fmaxf(v.y + bb.y, 0.f);
                v.z = fmaxf(v.z + bb.z, 0.f);
                v.w = fmaxf(v.w + bb.w, 0.f);
            }
        }
        sX4[j] = v;
    }
    __syncthreads();

    int warp = t >> 5, lane = t & 31;
    const float4* xr4 = (const float4*)&sX[warp * 8 * NC];
    unsigned long long acc2[8][2];
    #pragma unroll
    for (int r = 0; r < 8; r++) { acc2[r][0] = 0ull; acc2[r][1] = 0ull; }

    const float4* W4 = (const float4*)W;
    for (int k4 = 0; k4 < NC / 4; k4++) {
        float4 xv[8];
        #pragma unroll
        for (int r = 0; r < 8; r++) xv[r] = xr4[r * 32 + k4];
        #pragma unroll
        for (int kk = 0; kk < 4; kk++) {
            float4 w = __ldg(&W4[(k4 * 4 + kk) * 32 + lane]);
            unsigned long long wlo = pk2(w.x, w.y);
            unsigned long long whi = pk2(w.z, w.w);
            #pragma unroll
            for (int r = 0; r < 8; r++) {
                float e = (&xv[r].x)[kk];
                unsigned long long ee = pk2(e, e);
                acc2[r][0] = fma2(ee, wlo, acc2[r][0]);
                acc2[r][1] = fma2(ee, whi, acc2[r][1]);
            }
        }
    }

    float4 attv = *(const float4*)&sAtt[lane * 4];
    float4 wv   = *(const float4*)&sW[lane * 4];
    const float* xr = &sX[warp * 8 * NC];
    #pragma unroll
    for (int r = 0; r < 8; r++) {
        int gr = row0 + warp * 8 + r;
        if (gr < n) {
            float2 lo = upk2(acc2[r][0]);
            float2 hi = upk2(acc2[r][1]);
            float4 a = make_float4(lo.x, lo.y, hi.x, hi.y);
            union { __half2 h[2]; uint2 u; } cv;
            cv.h[0] = __floats2half2_rn(a.x, a.y);
            cv.h[1] = __floats2half2_rn(a.z, a.w);
            *(uint2*)&g_h16[(size_t)gr * NC + lane * 4] = cv.u;

            float pa = a.x * attv.x + a.y * attv.y + a.z * attv.z + a.w * attv.w;
            const float* xrow = xr + r * NC;
            float pd = xrow[lane * 4 + 0] * wv.x + xrow[lane * 4 + 1] * wv.y +
                       xrow[lane * 4 + 2] * wv.z + xrow[lane * 4 + 3] * wv.w;
            #pragma unroll
            for (int o = 16; o > 0; o >>= 1) {
                pa += __shfl_xor_sync(0xffffffffu, pa, o);
                pd += __shfl_xor_sync(0xffffffffu, pd, o);
            }
            if (lane == 0) { g_asrc[gr] = pa; g_adst[gr] = pd; }
        }
    }
}

// K4/K6: single-pass fused softmax + CSR aggregation (fp16 gather), warp per node.
__global__ void aggregate_fused(const float* __restrict__ bias2, int layer, int n) {
    int node = (blockIdx.x * blockDim.x + threadIdx.x) >> 5;
    int lane = threadIdx.x & 31;
    if (node >= n) return;
    int start = g_rowstart[node];
    int cnt   = g_deg[node];
    float adst = g_adst[node];

    float dsum = 0.f;
    float4 acc = make_float4(0.f, 0.f, 0.f, 0.f);

    for (int j0 = 0; j0 < cnt; j0 += 32) {
        int j = j0 + lane;
        int sN = 0; float w = 0.f;
        if (j < cnt) {
            sN = g_csr[start + j];
            float v = g_asrc[sN] + adst;
            v = (v >= 0.f) ? v : 0.2f * v;
            w = __expf(v);
        }
        dsum += w;
        int m = cnt - j0; if (m > 32) m = 32;
        int k = 0;
        for (; k + 8 <= m; k += 8) {
            int   si[8]; float wi[8]; uint2 raw[8];
            #pragma unroll
            for (int q = 0; q < 8; q++) {
                si[q] = __shfl_sync(0xffffffffu, sN, k + q);
                wi[q] = __shfl_sync(0xffffffffu, w, k + q);
            }
            #pragma unroll
            for (int q = 0; q < 8; q++)
                raw[q] = *(const uint2*)&g_h16[(size_t)si[q] * NC + lane * 4];
            #pragma unroll
            for (int q = 0; q < 8; q++) {
                float2 f0 = __half22float2(*(__half2*)&raw[q].x);
                float2 f1 = __half22float2(*(__half2*)&raw[q].y);
                acc.x += wi[q] * f0.x; acc.y += wi[q] * f0.y;
                acc.z += wi[q] * f1.x; acc.w += wi[q] * f1.y;
            }
        }
        for (; k < m; k++) {
            int   sk = __shfl_sync(0xffffffffu, sN, k);
            float wk = __shfl_sync(0xffffffffu, w, k);
            uint2 raw = *(const uint2*)&g_h16[(size_t)sk * NC + lane * 4];
            float2 f0 = __half22float2(*(__half2*)&raw.x);
            float2 f1 = __half22float2(*(__half2*)&raw.y);
            acc.x += wk * f0.x; acc.y += wk * f0.y;
            acc.z += wk * f1.x; acc.w += wk * f1.y;
        }
    }

    #pragma unroll
    for (int o = 16; o > 0; o >>= 1) dsum += __shfl_xor_sync(0xffffffffu, dsum, o);
    float inv = 1.f / (dsum + 1e-16f);
    acc.x *= inv; acc.y *= inv; acc.z *= inv; acc.w *= inv;

    if (layer == 0) {
        *(float4*)&g_agg[(size_t)node * NC + lane * 4] = acc;
    } else {
        int g = g_batch[node];
        float b0 = bias2[lane * 4 + 0], b1 = bias2[lane * 4 + 1];
        float b2 = bias2[lane * 4 + 2], b3 = bias2[lane * 4 + 3];
        float* dstp = &g_pool[g * NC + lane * 4];
        atomicAdd(dstp + 0, fmaxf(acc.x + b0, 0.f));
        atomicAdd(dstp + 1, fmaxf(acc.y + b1, 0.f));
        atomicAdd(dstp + 2, fmaxf(acc.z + b2, 0.f));
        atomicAdd(dstp + 3, fmaxf(acc.w + b3, 0.f));
        if (lane == 0) atomicAdd(&g_cnt[g], 1.0f);
    }
}

// K7: out = (pool/cnt) @ W_lin + b_lin  (64 x 128)
__global__ void final_linear(const float* __restrict__ Wl, const float* __restrict__ bl,
                             float* __restrict__ out) {
    __shared__ __align__(16) float sP[NC];
    int g = blockIdx.x, c = threadIdx.x;
    sP[c] = g_pool[g * NC + c] / fmaxf(g_cnt[g], 1.0f);
    __syncthreads();
    float acc = bl[c];
    #pragma unroll 4
    for (int k = 0; k < NC; k++) acc += sP[k] * Wl[k * NC + c];
    out[g * NC + c] = acc;
}

extern "C" void kernel_launch(void* const* d_in, const int* in_sizes, int n_in,
                              void* d_out, int out_size) {
    const float* x     = (const float*)d_in[0];
    const void*  ei    = d_in[1];
    const void*  batch = d_in[2];
    const float* Wsrc1   = (const float*)d_in[3];
    const float* Wdst1   = (const float*)d_in[4];
    const float* attsrc1 = (const float*)d_in[5];
    const float* attdst1 = (const float*)d_in[6];
    const float* bias1   = (const float*)d_in[7];
    const float* Wsrc2   = (const float*)d_in[8];
    const float* Wdst2   = (const float*)d_in[9];
    const float* attsrc2 = (const float*)d_in[10];
    const float* attdst2 = (const float*)d_in[11];
    const float* bias2   = (const float*)d_in[12];
    const float* Wlin    = (const float*)d_in[13];
    const float* blin    = (const float*)d_in[14];

    int n = in_sizes[0] / NC;
    int E = in_sizes[1] / 2;

    int gemm_blocks = (n + 63) / 64;
    int warp_blocks = (n + 7) / 8;

    // 1: prep (persistent; zero+fold, barrier, convert+hist)
    mega_prep<<<PBLK, 256>>>(Wdst1, attdst1, Wdst2, attdst2, ei, batch, E, n);
    // 2: layer-1 GEMM (independent of CSR)
    node_gemm<<<gemm_blocks, 256>>>(x, nullptr, Wsrc1, attsrc1, 0, n);
    // 3: scan + fill (persistent, internal barriers)
    scan_fill_kernel<<<PBLK, 256>>>(n, E);
    // 4: layer-1 aggregate  <-- ncu capture slot
    aggregate_fused<<<warp_blocks, 256>>>(nullptr, 0, n);
    // 5: layer-2 GEMM
    node_gemm<<<gemm_blocks, 256>>>(nullptr, bias1, Wsrc2, attsrc2, 1, n);
    // 6: layer-2 aggregate (pool fused)
    aggregate_fused<<<warp_blocks, 256>>>(bias2, 1, n);
    // 7: head
    final_linear<<<NG, NC>>>(Wlin, blin, (float*)d_out);
}

// round 10
// speedup vs baseline: 1.6416x; 1.4876x over previous
#include <cuda_runtime.h>
#include <cuda_fp16.h>
#include <math.h>

#define NC 128          // hidden / input dim
#define N_MAX 50000
#define E_MAX 800000
#define NG 64
#define PBLK 148        // persistent kernels: 1 block/SM, all resident

// ---- scratch (static device globals; no allocation allowed) ----
__device__ __half g_h16[(size_t)N_MAX * NC];   // h in fp16 (gather payload only)
__device__ float g_agg[(size_t)N_MAX * NC];
__device__ float g_asrc[N_MAX];
__device__ float g_adst[N_MAX];
__device__ float g_wdst1[NC];
__device__ float g_wdst2[NC];
__device__ int g_src[E_MAX];
__device__ int g_dst[E_MAX];
__device__ int g_batch[N_MAX];
__device__ int g_deg[N_MAX];
__device__ int g_rowstart[N_MAX];
__device__ int g_cursor[N_MAX];
__device__ int g_csr[E_MAX];
__device__ int g_bsum[PBLK];
// monotonically-increasing grid barrier state (epoch-based; replay-safe)
__device__ unsigned g_bar_cnt;
__device__ unsigned g_bar_rel;

__device__ __forceinline__ void grid_barrier(unsigned nblocks) {
    __threadfence();
    __syncthreads();
    if (threadIdx.x == 0) {
        unsigned my = atomicAdd(&g_bar_cnt, 1u) + 1u;
        unsigned epoch = (my + nblocks - 1u) / nblocks;
        if (my % nblocks == 0u) atomicAdd(&g_bar_rel, 1u);
        while (atomicAdd(&g_bar_rel, 0u) < epoch) __nanosleep(128);
        __threadfence();
    }
    __syncthreads();
}

// ---- packed f32x2 helpers (sm_103a FFMA2 path; ptxas won't emit from C++) ----
__device__ __forceinline__ unsigned long long pk2(float lo, float hi) {
    unsigned long long r;
    asm("mov.b64 %0, {%1, %2};" : "=l"(r) : "f"(lo), "f"(hi));
    return r;
}
__device__ __forceinline__ unsigned long long fma2(unsigned long long a,
                                                   unsigned long long b,
                                                   unsigned long long c) {
    unsigned long long d;
    asm("fma.rn.f32x2 %0, %1, %2, %3;" : "=l"(d) : "l"(a), "l"(b), "l"(c));
    return d;
}
__device__ __forceinline__ float2 upk2(unsigned long long v) {
    float x, y;
    asm("mov.b64 {%0, %1}, %2;" : "=f"(x), "=f"(y) : "l"(v));
    return make_float2(x, y);
}

// K1 (persistent): zero deg + fold wdst, BARRIER, detect+convert+hist.
__global__ void __launch_bounds__(256) mega_prep(
        const float* __restrict__ Wd1, const float* __restrict__ ad1,
        const float* __restrict__ Wd2, const float* __restrict__ ad2,
        const void* __restrict__ ei, const void* __restrict__ batch,
        int E, int n) {
    int tid = threadIdx.x, b = blockIdx.x;
    int gstep = PBLK * 256;
    int gt = b * 256 + tid;

    for (int i = gt; i < n; i += gstep) g_deg[i] = 0;
    if (b == 0) {
        if (tid < NC) {
            float s = 0.f;
            #pragma unroll 4
            for (int c = 0; c < NC; c++) s += Wd1[tid * NC + c] * ad1[c];
            g_wdst1[tid] = s;
        } else {
            int k = tid - NC;
            float s = 0.f;
            #pragma unroll 4
            for (int c = 0; c < NC; c++) s += Wd2[k * NC + c] * ad2[c];
            g_wdst2[k] = s;
        }
    }

    __shared__ int s_or;
    if (tid == 0) s_or = 0;
    __syncthreads();
    {
        const int* w = (const int*)ei;
        int cnt = (E < 2048) ? E : 2048;
        int acc = 0;
        for (int i = tid; i < cnt; i += 256) acc |= w[2 * i + 1];
        atomicOr(&s_or, acc);
    }
    __syncthreads();
    int is64 = (s_or == 0) ? 1 : 0;

    grid_barrier(PBLK);

    for (int i = gt; i < E; i += gstep) {
        int s, d;
        if (is64) {
            s = (int)((const long long*)ei)[i];
            d = (int)((const long long*)ei)[E + i];
        } else {
            s = ((const int*)ei)[i];
            d = ((const int*)ei)[E + i];
        }
        g_src[i] = s;
        g_dst[i] = d;
        atomicAdd(&g_deg[d], 1);
    }
    for (int i = gt; i < n; i += gstep)
        g_batch[i] = is64 ? (int)((const long long*)batch)[i] : ((const int*)batch)[i];
}

// K3 (persistent): degree scan (block-local + cross-block) then CSR fill.
__global__ void __launch_bounds__(256) scan_fill_kernel(int n, int E) {
    __shared__ int sS[256];
    __shared__ int sBase;
    int tid = threadIdx.x, b = blockIdx.x;
    int C = (n + PBLK - 1) / PBLK;
    int ept = (C + 255) / 256;
    int nb1 = min(n, (b + 1) * C);
    int t0 = b * C + tid * ept;

    int s = 0;
    for (int i = 0; i < ept; i++) {
        int idx = t0 + i;
        if (idx < nb1) s += g_deg[idx];
    }
    sS[tid] = s;
    __syncthreads();
    for (int off = 1; off < 256; off <<= 1) {
        int v = (tid >= off) ? sS[tid - off] : 0;
        __syncthreads();
        sS[tid] += v;
        __syncthreads();
    }
    int excl = sS[tid] - s;
    if (tid == 255) g_bsum[b] = sS[255];

    grid_barrier(PBLK);

    if (tid == 0) {
        int base = 0;
        for (int i = 0; i < b; i++) base += g_bsum[i];
        sBase = base;
    }
    __syncthreads();
    int base = sBase + excl;
    for (int i = 0; i < ept; i++) {
        int idx = t0 + i;
        if (idx < nb1) {
            g_rowstart[idx] = base;
            g_cursor[idx]   = base;
            base += g_deg[idx];
        }
    }

    grid_barrier(PBLK);

    for (int e = b * 256 + tid; e < E; e += PBLK * 256) {
        int slot = atomicAdd(&g_cursor[g_dst[e]], 1);
        g_csr[slot] = g_src[e];
    }
}

// K2/K5: node GEMM with packed f32x2 FMA. 64 rows/block, warp handles 8 rows.
__global__ void __launch_bounds__(256) node_gemm(
        const float* __restrict__ X_ext, const float* __restrict__ bias_in,
        const float* __restrict__ W, const float* __restrict__ att,
        int layer, int n) {
    __shared__ __align__(16) float sX[64 * NC];
    __shared__ __align__(16) float sAtt[NC];
    __shared__ __align__(16) float sW[NC];
    int t = threadIdx.x;
    int row0 = blockIdx.x * 64;
    const float* wdst = (layer == 0) ? g_wdst1 : g_wdst2;
    const float* X    = (layer == 0) ? X_ext : g_agg;
    if (t < NC) sAtt[t] = att[t];
    else        sW[t - NC] = wdst[t - NC];

    float4* sX4 = (float4*)sX;
    const float4* X4 = (const float4*)X;
    const float4* B4 = (const float4*)bias_in;
    #pragma unroll
    for (int i = 0; i < 8; i++) {
        int j = i * 256 + t;
        int r = j >> 5, c4 = j & 31;
        int gr = row0 + r;
        float4 v = make_float4(0.f, 0.f, 0.f, 0.f);
        if (gr < n) {
            v = X4[(size_t)gr * 32 + c4];
            if (layer == 1) {
                float4 bb = B4[c4];
                v.x = fmaxf(v.x + bb.x, 0.f);
                v.y = fmaxf(v.y + bb.y, 0.f);
                v.z = fmaxf(v.z + bb.z, 0.f);
                v.w = fmaxf(v.w + bb.w, 0.f);
            }
        }
        sX4[j] = v;
    }
    __syncthreads();

    int warp = t >> 5, lane = t & 31;
    const float4* xr4 = (const float4*)&sX[warp * 8 * NC];
    unsigned long long acc2[8][2];
    #pragma unroll
    for (int r = 0; r < 8; r++) { acc2[r][0] = 0ull; acc2[r][1] = 0ull; }

    const float4* W4 = (const float4*)W;
    for (int k4 = 0; k4 < NC / 4; k4++) {
        float4 xv[8];
        #pragma unroll
        for (int r = 0; r < 8; r++) xv[r] = xr4[r * 32 + k4];
        #pragma unroll
        for (int kk = 0; kk < 4; kk++) {
            float4 w = __ldg(&W4[(k4 * 4 + kk) * 32 + lane]);
            unsigned long long wlo = pk2(w.x, w.y);
            unsigned long long whi = pk2(w.z, w.w);
            #pragma unroll
            for (int r = 0; r < 8; r++) {
                float e = (&xv[r].x)[kk];
                unsigned long long ee = pk2(e, e);
                acc2[r][0] = fma2(ee, wlo, acc2[r][0]);
                acc2[r][1] = fma2(ee, whi, acc2[r][1]);
            }
        }
    }

    float4 attv = *(const float4*)&sAtt[lane * 4];
    float4 wv   = *(const float4*)&sW[lane * 4];
    const float* xr = &sX[warp * 8 * NC];
    #pragma unroll
    for (int r = 0; r < 8; r++) {
        int gr = row0 + warp * 8 + r;
        if (gr < n) {
            float2 lo = upk2(acc2[r][0]);
            float2 hi = upk2(acc2[r][1]);
            float4 a = make_float4(lo.x, lo.y, hi.x, hi.y);
            union { __half2 h[2]; uint2 u; } cv;
            cv.h[0] = __floats2half2_rn(a.x, a.y);
            cv.h[1] = __floats2half2_rn(a.z, a.w);
            *(uint2*)&g_h16[(size_t)gr * NC + lane * 4] = cv.u;

            float pa = a.x * attv.x + a.y * attv.y + a.z * attv.z + a.w * attv.w;
            const float* xrow = xr + r * NC;
            float pd = xrow[lane * 4 + 0] * wv.x + xrow[lane * 4 + 1] * wv.y +
                       xrow[lane * 4 + 2] * wv.z + xrow[lane * 4 + 3] * wv.w;
            #pragma unroll
            for (int o = 16; o > 0; o >>= 1) {
                pa += __shfl_xor_sync(0xffffffffu, pa, o);
                pd += __shfl_xor_sync(0xffffffffu, pd, o);
            }
            if (lane == 0) { g_asrc[gr] = pa; g_adst[gr] = pd; }
        }
    }
}

// K4/K6: single-pass fused softmax + CSR aggregation (fp16 gather), warp per node.
// Always writes g_agg (no atomics anywhere).
__global__ void aggregate_fused(int n) {
    int node = (blockIdx.x * blockDim.x + threadIdx.x) >> 5;
    int lane = threadIdx.x & 31;
    if (node >= n) return;
    int start = g_rowstart[node];
    int cnt   = g_deg[node];
    float adst = g_adst[node];

    float dsum = 0.f;
    float4 acc = make_float4(0.f, 0.f, 0.f, 0.f);

    for (int j0 = 0; j0 < cnt; j0 += 32) {
        int j = j0 + lane;
        int sN = 0; float w = 0.f;
        if (j < cnt) {
            sN = g_csr[start + j];
            float v = g_asrc[sN] + adst;
            v = (v >= 0.f) ? v : 0.2f * v;
            w = __expf(v);
        }
        dsum += w;
        int m = cnt - j0; if (m > 32) m = 32;
        int k = 0;
        for (; k + 8 <= m; k += 8) {
            int   si[8]; float wi[8]; uint2 raw[8];
            #pragma unroll
            for (int q = 0; q < 8; q++) {
                si[q] = __shfl_sync(0xffffffffu, sN, k + q);
                wi[q] = __shfl_sync(0xffffffffu, w, k + q);
            }
            #pragma unroll
            for (int q = 0; q < 8; q++)
                raw[q] = *(const uint2*)&g_h16[(size_t)si[q] * NC + lane * 4];
            #pragma unroll
            for (int q = 0; q < 8; q++) {
                float2 f0 = __half22float2(*(__half2*)&raw[q].x);
                float2 f1 = __half22float2(*(__half2*)&raw[q].y);
                acc.x += wi[q] * f0.x; acc.y += wi[q] * f0.y;
                acc.z += wi[q] * f1.x; acc.w += wi[q] * f1.y;
            }
        }
        for (; k < m; k++) {
            int   sk = __shfl_sync(0xffffffffu, sN, k);
            float wk = __shfl_sync(0xffffffffu, w, k);
            uint2 raw = *(const uint2*)&g_h16[(size_t)sk * NC + lane * 4];
            float2 f0 = __half22float2(*(__half2*)&raw.x);
            float2 f1 = __half22float2(*(__half2*)&raw.y);
            acc.x += wk * f0.x; acc.y += wk * f0.y;
            acc.z += wk * f1.x; acc.w += wk * f1.y;
        }
    }

    #pragma unroll
    for (int o = 16; o > 0; o >>= 1) dsum += __shfl_xor_sync(0xffffffffu, dsum, o);
    float inv = 1.f / (dsum + 1e-16f);
    acc.x *= inv; acc.y *= inv; acc.z *= inv; acc.w *= inv;

    *(float4*)&g_agg[(size_t)node * NC + lane * 4] = acc;
}

// K7: fused mean-pool + head. One block per graph (batch is SORTED).
// pooled[c] = mean over nodes i in graph g of relu(g_agg[i,c] + bias2[c])
// out[g,c]  = sum_k pooled[k] * Wl[k,c] + bl[c]
__global__ void __launch_bounds__(NC) pool_head(
        const float* __restrict__ bias2, const float* __restrict__ Wl,
        const float* __restrict__ bl, float* __restrict__ out, int n) {
    __shared__ __align__(16) float sP[NC];
    __shared__ int sLo, sHi;
    int g = blockIdx.x, c = threadIdx.x;

    if (c == 0) {
        // lower_bound(g) over sorted g_batch
        int lo = 0, hi = n;
        while (lo < hi) { int mid = (lo + hi) >> 1; if (g_batch[mid] < g) lo = mid + 1; else hi = mid; }
        sLo = lo;
        lo = 0; hi = n;
        while (lo < hi) { int mid = (lo + hi) >> 1; if (g_batch[mid] < g + 1) lo = mid + 1; else hi = mid; }
        sHi = lo;
    }
    __syncthreads();
    int s = sLo, e = sHi;
    float b = bias2[c];
    float acc = 0.f;
    for (int i = s; i < e; i++)
        acc += fmaxf(g_agg[(size_t)i * NC + c] + b, 0.f);
    float cntf = (float)(e - s);
    sP[c] = acc / fmaxf(cntf, 1.0f);
    __syncthreads();

    float o = bl[c];
    #pragma unroll 4
    for (int k = 0; k < NC; k++) o += sP[k] * Wl[k * NC + c];
    out[g * NC + c] = o;
}

extern "C" void kernel_launch(void* const* d_in, const int* in_sizes, int n_in,
                              void* d_out, int out_size) {
    const float* x     = (const float*)d_in[0];
    const void*  ei    = d_in[1];
    const void*  batch = d_in[2];
    const float* Wsrc1   = (const float*)d_in[3];
    const float* Wdst1   = (const float*)d_in[4];
    const float* attsrc1 = (const float*)d_in[5];
    const float* attdst1 = (const float*)d_in[6];
    const float* bias1   = (const float*)d_in[7];
    const float* Wsrc2   = (const float*)d_in[8];
    const float* Wdst2   = (const float*)d_in[9];
    const float* attsrc2 = (const float*)d_in[10];
    const float* attdst2 = (const float*)d_in[11];
    const float* bias2   = (const float*)d_in[12];
    const float* Wlin    = (const float*)d_in[13];
    const float* blin    = (const float*)d_in[14];

    int n = in_sizes[0] / NC;
    int E = in_sizes[1] / 2;

    int gemm_blocks = (n + 63) / 64;
    int warp_blocks = (n + 7) / 8;

    mega_prep<<<PBLK, 256>>>(Wdst1, attdst1, Wdst2, attdst2, ei, batch, E, n);
    node_gemm<<<gemm_blocks, 256>>>(x, nullptr, Wsrc1, attsrc1, 0, n);
    scan_fill_kernel<<<PBLK, 256>>>(n, E);
    aggregate_fused<<<warp_blocks, 256>>>(n);          // slot 4: ncu control
    node_gemm<<<gemm_blocks, 256>>>(nullptr, bias1, Wsrc2, attsrc2, 1, n);
    aggregate_fused<<<warp_blocks, 256>>>(n);
    pool_head<<<NG, NC>>>(bias2, Wlin, blin, (float*)d_out, n);
}

// round 11
// speedup vs baseline: 2.1524x; 1.3112x over previous
#include <cuda_runtime.h>
#include <cuda_fp16.h>
#include <math.h>

#define NC 128          // hidden / input dim
#define N_MAX 50000
#define E_MAX 800000
#define NG 64
#define PBLK 148        // persistent kernels: 1 block/SM, all resident
#define SA_LD 136       // padded smem stride in halves (272B: 16B-aligned rows, conflict-free ldmatrix)

// ---- scratch (static device globals; no allocation allowed) ----
__device__ __half g_h16[(size_t)N_MAX * NC];   // h (gemm output, gather payload)
__device__ __half g_x16[(size_t)N_MAX * NC];   // gemm input (fp16)
__device__ __half g_w16a[NC * NC];             // W_src1 fp16
__device__ __half g_w16b[NC * NC];             // W_src2 fp16
__device__ float g_agg[(size_t)N_MAX * NC];
__device__ float g_asrc[N_MAX];
__device__ float g_adst[N_MAX];
__device__ float g_wdst1[NC];
__device__ float g_wdst2[NC];
__device__ int g_src[E_MAX];
__device__ int g_dst[E_MAX];
__device__ int g_batch[N_MAX];
__device__ int g_deg[N_MAX];
__device__ int g_rowstart[N_MAX];
__device__ int g_cursor[N_MAX];
__device__ int g_csr[E_MAX];
__device__ int g_bsum[PBLK];
__device__ unsigned g_bar_cnt;
__device__ unsigned g_bar_rel;

__device__ __forceinline__ void grid_barrier(unsigned nblocks) {
    __threadfence();
    __syncthreads();
    if (threadIdx.x == 0) {
        unsigned my = atomicAdd(&g_bar_cnt, 1u) + 1u;
        unsigned epoch = (my + nblocks - 1u) / nblocks;
        if (my % nblocks == 0u) atomicAdd(&g_bar_rel, 1u);
        while (atomicAdd(&g_bar_rel, 0u) < epoch) __nanosleep(128);
        __threadfence();
    }
    __syncthreads();
}

// K1 (persistent): zero deg + fold wdst + fp16 conversions, BARRIER, convert+hist.
__global__ void __launch_bounds__(256) mega_prep(
        const float* __restrict__ x,
        const float* __restrict__ Ws1, const float* __restrict__ Ws2,
        const float* __restrict__ Wd1, const float* __restrict__ ad1,
        const float* __restrict__ Wd2, const float* __restrict__ ad2,
        const void* __restrict__ ei, const void* __restrict__ batch,
        int E, int n) {
    int tid = threadIdx.x, b = blockIdx.x;
    int gstep = PBLK * 256;
    int gt = b * 256 + tid;

    for (int i = gt; i < n; i += gstep) g_deg[i] = 0;
    if (b == 0) {
        if (tid < NC) {
            float s = 0.f;
            #pragma unroll 4
            for (int c = 0; c < NC; c++) s += Wd1[tid * NC + c] * ad1[c];
            g_wdst1[tid] = s;
        } else {
            int k = tid - NC;
            float s = 0.f;
            #pragma unroll 4
            for (int c = 0; c < NC; c++) s += Wd2[k * NC + c] * ad2[c];
            g_wdst2[k] = s;
        }
    }

    // fp16 conversions: x (n*32 float4s), W1/W2 (4096 float4s each)
    int total4 = n * (NC / 4);
    const float4* X4 = (const float4*)x;
    uint2* X16o = (uint2*)g_x16;
    for (int i = gt; i < total4; i += gstep) {
        float4 v = X4[i];
        union { __half2 h[2]; uint2 u; } cv;
        cv.h[0] = __floats2half2_rn(v.x, v.y);
        cv.h[1] = __floats2half2_rn(v.z, v.w);
        X16o[i] = cv.u;
    }
    const float4* W14 = (const float4*)Ws1;
    const float4* W24 = (const float4*)Ws2;
    uint2* W1o = (uint2*)g_w16a;
    uint2* W2o = (uint2*)g_w16b;
    for (int i = gt; i < NC * NC / 4; i += gstep) {
        float4 v = W14[i];
        union { __half2 h[2]; uint2 u; } cv;
        cv.h[0] = __floats2half2_rn(v.x, v.y);
        cv.h[1] = __floats2half2_rn(v.z, v.w);
        W1o[i] = cv.u;
        v = W24[i];
        cv.h[0] = __floats2half2_rn(v.x, v.y);
        cv.h[1] = __floats2half2_rn(v.z, v.w);
        W2o[i] = cv.u;
    }

    __shared__ int s_or;
    if (tid == 0) s_or = 0;
    __syncthreads();
    {
        const int* w = (const int*)ei;
        int cnt = (E < 2048) ? E : 2048;
        int acc = 0;
        for (int i = tid; i < cnt; i += 256) acc |= w[2 * i + 1];
        atomicOr(&s_or, acc);
    }
    __syncthreads();
    int is64 = (s_or == 0) ? 1 : 0;

    grid_barrier(PBLK);

    for (int i = gt; i < E; i += gstep) {
        int s, d;
        if (is64) {
            s = (int)((const long long*)ei)[i];
            d = (int)((const long long*)ei)[E + i];
        } else {
            s = ((const int*)ei)[i];
            d = ((const int*)ei)[E + i];
        }
        g_src[i] = s;
        g_dst[i] = d;
        atomicAdd(&g_deg[d], 1);
    }
    for (int i = gt; i < n; i += gstep)
        g_batch[i] = is64 ? (int)((const long long*)batch)[i] : ((const int*)batch)[i];
}

// K2 (persistent): degree scan then CSR fill.
__global__ void __launch_bounds__(256) scan_fill_kernel(int n, int E) {
    __shared__ int sS[256];
    __shared__ int sBase;
    int tid = threadIdx.x, b = blockIdx.x;
    int C = (n + PBLK - 1) / PBLK;
    int ept = (C + 255) / 256;
    int nb1 = min(n, (b + 1) * C);
    int t0 = b * C + tid * ept;

    int s = 0;
    for (int i = 0; i < ept; i++) {
        int idx = t0 + i;
        if (idx < nb1) s += g_deg[idx];
    }
    sS[tid] = s;
    __syncthreads();
    for (int off = 1; off < 256; off <<= 1) {
        int v = (tid >= off) ? sS[tid - off] : 0;
        __syncthreads();
        sS[tid] += v;
        __syncthreads();
    }
    int excl = sS[tid] - s;
    if (tid == 255) g_bsum[b] = sS[255];

    grid_barrier(PBLK);

    if (tid == 0) {
        int base = 0;
        for (int i = 0; i < b; i++) base += g_bsum[i];
        sBase = base;
    }
    __syncthreads();
    int base = sBase + excl;
    for (int i = 0; i < ept; i++) {
        int idx = t0 + i;
        if (idx < nb1) {
            g_rowstart[idx] = base;
            g_cursor[idx]   = base;
            base += g_deg[idx];
        }
    }

    grid_barrier(PBLK);

    for (int e = b * 256 + tid; e < E; e += PBLK * 256) {
        int slot = atomicAdd(&g_cursor[g_dst[e]], 1);
        g_csr[slot] = g_src[e];
    }
}

// K3/K5: HMMA node GEMM. CTA = 128 rows x 128 cols x K=128, 8 warps.
// Reads g_x16 (fp16 input), g_w16a/b. Writes g_h16, g_asrc, g_adst.
__global__ void __launch_bounds__(256) hmma_gemm(const float* __restrict__ att,
                                                 int layer, int n) {
    extern __shared__ __half smem[];
    __half* sA = smem;                        // 128 x SA_LD
    __half* sB = smem + 128 * SA_LD;          // 128 x SA_LD (W: [k][n])
    __shared__ __align__(16) float sAtt[NC];
    __shared__ __align__(16) float sW[NC];

    int t = threadIdx.x;
    int row0 = blockIdx.x * 128;
    const __half* W16 = (layer == 0) ? g_w16a : g_w16b;
    const float* wdst = (layer == 0) ? g_wdst1 : g_wdst2;
    if (t < NC) sAtt[t] = att[t];
    else        sW[t - NC] = wdst[t - NC];

    // stage A (input rows, zero-padded) and B (weights)
    #pragma unroll
    for (int i = 0; i < 8; i++) {
        int j = i * 256 + t;            // 0..2047 chunks of 8 halves
        int r = j >> 4, c8 = j & 15;
        int gr = row0 + r;
        uint4 v = make_uint4(0u, 0u, 0u, 0u);
        if (gr < n) v = *(const uint4*)&g_x16[(size_t)gr * NC + c8 * 8];
        *(uint4*)&sA[r * SA_LD + c8 * 8] = v;
        uint4 wv = *(const uint4*)&W16[r * NC + c8 * 8];
        *(uint4*)&sB[r * SA_LD + c8 * 8] = wv;
    }
    __syncthreads();

    int warp = t >> 5, lane = t & 31;
    int rbase = warp * 16;

    float acc[16][4];
    #pragma unroll
    for (int j = 0; j < 16; j++)
        { acc[j][0] = 0.f; acc[j][1] = 0.f; acc[j][2] = 0.f; acc[j][3] = 0.f; }

    // ldmatrix source addresses
    int a_row = rbase + (lane & 7) + ((lane >> 3) & 1) * 8;
    int a_colsel = ((lane >> 4) & 1) * 8;
    int b_krow_in16 = (lane & 7) + ((lane >> 3) & 1) * 8;   // lanes 0-15 meaningful

    #pragma unroll
    for (int kk = 0; kk < 8; kk++) {
        unsigned a0, a1, a2, a3;
        {
            unsigned aaddr = (unsigned)__cvta_generic_to_shared(
                &sA[a_row * SA_LD + kk * 16 + a_colsel]);
            asm volatile("ldmatrix.sync.aligned.m8n8.x4.shared.b16 {%0,%1,%2,%3}, [%4];"
                         : "=r"(a0), "=r"(a1), "=r"(a2), "=r"(a3) : "r"(aaddr));
        }
        #pragma unroll
        for (int j = 0; j < 16; j++) {
            unsigned b0, b1;
            unsigned baddr = (unsigned)__cvta_generic_to_shared(
                &sB[(kk * 16 + b_krow_in16) * SA_LD + j * 8]);
            asm volatile("ldmatrix.sync.aligned.m8n8.x2.trans.shared.b16 {%0,%1}, [%2];"
                         : "=r"(b0), "=r"(b1) : "r"(baddr));
            asm volatile(
                "mma.sync.aligned.m16n8k16.row.col.f32.f16.f16.f32 "
                "{%0,%1,%2,%3}, {%4,%5,%6,%7}, {%8,%9}, {%0,%1,%2,%3};"
                : "+f"(acc[j][0]), "+f"(acc[j][1]), "+f"(acc[j][2]), "+f"(acc[j][3])
                : "r"(a0), "r"(a1), "r"(a2), "r"(a3), "r"(b0), "r"(b1));
        }
    }

    // epilogue: h16 store + asrc (attention score on h) per row
    int rL = row0 + rbase + (lane >> 2);       // rows (lane/4) and +8
    int rH = rL + 8;
    int colq = (lane & 3) * 2;
    float paL = 0.f, paH = 0.f;
    #pragma unroll
    for (int j = 0; j < 16; j++) {
        float2 av = *(const float2*)&sAtt[j * 8 + colq];
        paL += acc[j][0] * av.x + acc[j][1] * av.y;
        paH += acc[j][2] * av.x + acc[j][3] * av.y;
        if (rL < n)
            *(__half2*)&g_h16[(size_t)rL * NC + j * 8 + colq] =
                __floats2half2_rn(acc[j][0], acc[j][1]);
        if (rH < n)
            *(__half2*)&g_h16[(size_t)rH * NC + j * 8 + colq] =
                __floats2half2_rn(acc[j][2], acc[j][3]);
    }
    paL += __shfl_xor_sync(0xffffffffu, paL, 1);
    paL += __shfl_xor_sync(0xffffffffu, paL, 2);
    paH += __shfl_xor_sync(0xffffffffu, paH, 1);
    paH += __shfl_xor_sync(0xffffffffu, paH, 2);
    if ((lane & 3) == 0) {
        if (rL < n) g_asrc[rL] = paL;
        if (rH < n) g_asrc[rH] = paH;
    }

    // adst = X . wdst  (from staged fp16 input)
    for (int r = 0; r < 16; r++) {
        int gr = row0 + rbase + r;
        uint2 raw = *(const uint2*)&sA[(rbase + r) * SA_LD + lane * 4];
        float2 f0 = __half22float2(*(__half2*)&raw.x);
        float2 f1 = __half22float2(*(__half2*)&raw.y);
        const float4 wv = *(const float4*)&sW[lane * 4];
        float pd = f0.x * wv.x + f0.y * wv.y + f1.x * wv.z + f1.y * wv.w;
        #pragma unroll
        for (int o = 16; o > 0; o >>= 1) pd += __shfl_xor_sync(0xffffffffu, pd, o);
        if (lane == 0 && gr < n) g_adst[gr] = pd;
    }
}

// K4/K6: single-pass fused softmax + CSR aggregation (fp16 gather), warp per node.
// layer==0: writes g_x16 = fp16(relu(acc + bias1))  (layer-2 GEMM input)
// layer==1: writes g_agg fp32 (pool input)
__global__ void aggregate_fused(const float* __restrict__ bias1, int layer, int n) {
    int node = (blockIdx.x * blockDim.x + threadIdx.x) >> 5;
    int lane = threadIdx.x & 31;
    if (node >= n) return;
    int start = g_rowstart[node];
    int cnt   = g_deg[node];
    float adst = g_adst[node];

    float dsum = 0.f;
    float4 acc = make_float4(0.f, 0.f, 0.f, 0.f);

    for (int j0 = 0; j0 < cnt; j0 += 32) {
        int j = j0 + lane;
        int sN = 0; float w = 0.f;
        if (j < cnt) {
            sN = g_csr[start + j];
            float v = g_asrc[sN] + adst;
            v = (v >= 0.f) ? v : 0.2f * v;
            w = __expf(v);
        }
        dsum += w;
        int m = cnt - j0; if (m > 32) m = 32;
        int k = 0;
        for (; k + 8 <= m; k += 8) {
            int   si[8]; float wi[8]; uint2 raw[8];
            #pragma unroll
            for (int q = 0; q < 8; q++) {
                si[q] = __shfl_sync(0xffffffffu, sN, k + q);
                wi[q] = __shfl_sync(0xffffffffu, w, k + q);
            }
            #pragma unroll
            for (int q = 0; q < 8; q++)
                raw[q] = *(const uint2*)&g_h16[(size_t)si[q] * NC + lane * 4];
            #pragma unroll
            for (int q = 0; q < 8; q++) {
                float2 f0 = __half22float2(*(__half2*)&raw[q].x);
                float2 f1 = __half22float2(*(__half2*)&raw[q].y);
                acc.x += wi[q] * f0.x; acc.y += wi[q] * f0.y;
                acc.z += wi[q] * f1.x; acc.w += wi[q] * f1.y;
            }
        }
        for (; k < m; k++) {
            int   sk = __shfl_sync(0xffffffffu, sN, k);
            float wk = __shfl_sync(0xffffffffu, w, k);
            uint2 raw = *(const uint2*)&g_h16[(size_t)sk * NC + lane * 4];
            float2 f0 = __half22float2(*(__half2*)&raw.x);
            float2 f1 = __half22float2(*(__half2*)&raw.y);
            acc.x += wk * f0.x; acc.y += wk * f0.y;
            acc.z += wk * f1.x; acc.w += wk * f1.y;
        }
    }

    #pragma unroll
    for (int o = 16; o > 0; o >>= 1) dsum += __shfl_xor_sync(0xffffffffu, dsum, o);
    float inv = 1.f / (dsum + 1e-16f);
    acc.x *= inv; acc.y *= inv; acc.z *= inv; acc.w *= inv;

    if (layer == 0) {
        float4 b = *(const float4*)&bias1[lane * 4];
        union { __half2 h[2]; uint2 u; } cv;
        cv.h[0] = __floats2half2_rn(fmaxf(acc.x + b.x, 0.f), fmaxf(acc.y + b.y, 0.f));
        cv.h[1] = __floats2half2_rn(fmaxf(acc.z + b.z, 0.f), fmaxf(acc.w + b.w, 0.f));
        *(uint2*)&g_x16[(size_t)node * NC + lane * 4] = cv.u;
    } else {
        *(float4*)&g_agg[(size_t)node * NC + lane * 4] = acc;
    }
}

// K7: fused mean-pool + head. One block per graph (batch is SORTED).
__global__ void __launch_bounds__(NC) pool_head(
        const float* __restrict__ bias2, const float* __restrict__ Wl,
        const float* __restrict__ bl, float* __restrict__ out, int n) {
    __shared__ __align__(16) float sP[NC];
    __shared__ int sLo, sHi;
    int g = blockIdx.x, c = threadIdx.x;

    if (c == 0) {
        int lo = 0, hi = n;
        while (lo < hi) { int mid = (lo + hi) >> 1; if (g_batch[mid] < g) lo = mid + 1; else hi = mid; }
        sLo = lo;
        lo = 0; hi = n;
        while (lo < hi) { int mid = (lo + hi) >> 1; if (g_batch[mid] < g + 1) lo = mid + 1; else hi = mid; }
        sHi = lo;
    }
    __syncthreads();
    int s = sLo, e = sHi;
    float b = bias2[c];
    float acc = 0.f;
    for (int i = s; i < e; i++)
        acc += fmaxf(g_agg[(size_t)i * NC + c] + b, 0.f);
    float cntf = (float)(e - s);
    sP[c] = acc / fmaxf(cntf, 1.0f);
    __syncthreads();

    float o = bl[c];
    #pragma unroll 4
    for (int k = 0; k < NC; k++) o += sP[k] * Wl[k * NC + c];
    out[g * NC + c] = o;
}

extern "C" void kernel_launch(void* const* d_in, const int* in_sizes, int n_in,
                              void* d_out, int out_size) {
    const float* x     = (const float*)d_in[0];
    const void*  ei    = d_in[1];
    const void*  batch = d_in[2];
    const float* Wsrc1   = (const float*)d_in[3];
    const float* Wdst1   = (const float*)d_in[4];
    const float* attsrc1 = (const float*)d_in[5];
    const float* attdst1 = (const float*)d_in[6];
    const float* bias1   = (const float*)d_in[7];
    const float* Wsrc2   = (const float*)d_in[8];
    const float* Wdst2   = (const float*)d_in[9];
    const float* attsrc2 = (const float*)d_in[10];
    const float* attdst2 = (const float*)d_in[11];
    const float* bias2   = (const float*)d_in[12];
    const float* Wlin    = (const float*)d_in[13];
    const float* blin    = (const float*)d_in[14];

    int n = in_sizes[0] / NC;
    int E = in_sizes[1] / 2;

    int gemm_blocks = (n + 127) / 128;
    int warp_blocks = (n + 7) / 8;
    int gemm_smem   = 2 * 128 * SA_LD * (int)sizeof(__half);   // 69632 B

    static int attr_set = 0;
    if (!attr_set) {
        cudaFuncSetAttribute(hmma_gemm, cudaFuncAttributeMaxDynamicSharedMemorySize,
                             gemm_smem);
        attr_set = 1;
    }

    mega_prep<<<PBLK, 256>>>(x, Wsrc1, Wsrc2, Wdst1, attdst1, Wdst2, attdst2,
                             ei, batch, E, n);
    scan_fill_kernel<<<PBLK, 256>>>(n, E);
    hmma_gemm<<<gemm_blocks, 256, gemm_smem>>>(attsrc1, 0, n);
    aggregate_fused<<<warp_blocks, 256>>>(bias1, 0, n);
    hmma_gemm<<<gemm_blocks, 256, gemm_smem>>>(attsrc2, 1, n);
    aggregate_fused<<<warp_blocks, 256>>>(nullptr, 1, n);
    pool_head<<<NG, NC>>>(bias2, Wlin, blin, (float*)d_out, n);
}

// round 12
// speedup vs baseline: 2.3627x; 1.0977x over previous
#include <cuda_runtime.h>
#include <cuda_fp16.h>
#include <math.h>

#define NC 128          // hidden / input dim
#define N_MAX 50000
#define E_MAX 800000
#define NG 64
#define PBLK 592        // persistent kernels: 4 blocks/SM x 148 SMs, all resident
#define SA_LD 136       // padded smem stride in halves

// ---- scratch (static device globals; no allocation allowed) ----
__device__ __half g_h16[(size_t)N_MAX * NC];   // h (gemm output, gather payload)
__device__ __half g_x16[(size_t)N_MAX * NC];   // layer-2 gemm input (fp16)
__device__ __half g_w16a[NC * NC];             // W_src1 fp16
__device__ __half g_w16b[NC * NC];             // W_src2 fp16
__device__ float g_agg[(size_t)N_MAX * NC];
__device__ float g_asrc[N_MAX];
__device__ float g_adst[N_MAX];
__device__ float g_wdst1[NC];
__device__ float g_wdst2[NC];
__device__ int g_src[E_MAX];
__device__ int g_dst[E_MAX];
__device__ int g_batch[N_MAX];
__device__ int g_deg[N_MAX];
__device__ int g_rowstart[N_MAX];
__device__ int g_cursor[N_MAX];
__device__ int g_csr[E_MAX];
__device__ int g_bsum[PBLK];
__device__ unsigned g_bar_cnt;
__device__ unsigned g_bar_rel;

__device__ __forceinline__ void grid_barrier(unsigned nblocks) {
    __threadfence();
    __syncthreads();
    if (threadIdx.x == 0) {
        unsigned my = atomicAdd(&g_bar_cnt, 1u) + 1u;
        unsigned epoch = (my + nblocks - 1u) / nblocks;
        if (my % nblocks == 0u) atomicAdd(&g_bar_rel, 1u);
        while (atomicAdd(&g_bar_rel, 0u) < epoch) __nanosleep(128);
        __threadfence();
    }
    __syncthreads();
}

// K1 (persistent, 4 blocks/SM): zero deg + fold wdst + W fp16, BARRIER, convert+hist.
__global__ void __launch_bounds__(256, 4) mega_prep(
        const float* __restrict__ Ws1, const float* __restrict__ Ws2,
        const float* __restrict__ Wd1, const float* __restrict__ ad1,
        const float* __restrict__ Wd2, const float* __restrict__ ad2,
        const void* __restrict__ ei, const void* __restrict__ batch,
        int E, int n) {
    int tid = threadIdx.x, b = blockIdx.x;
    int gstep = PBLK * 256;
    int gt = b * 256 + tid;

    for (int i = gt; i < n; i += gstep) g_deg[i] = 0;
    if (b == 0) {
        if (tid < NC) {
            float s = 0.f;
            #pragma unroll 4
            for (int c = 0; c < NC; c++) s += Wd1[tid * NC + c] * ad1[c];
            g_wdst1[tid] = s;
        } else {
            int k = tid - NC;
            float s = 0.f;
            #pragma unroll 4
            for (int c = 0; c < NC; c++) s += Wd2[k * NC + c] * ad2[c];
            g_wdst2[k] = s;
        }
    }

    // W fp16 conversions (x conversion now fused into layer-0 gemm staging)
    const float4* W14 = (const float4*)Ws1;
    const float4* W24 = (const float4*)Ws2;
    uint2* W1o = (uint2*)g_w16a;
    uint2* W2o = (uint2*)g_w16b;
    for (int i = gt; i < NC * NC / 4; i += gstep) {
        float4 v = W14[i];
        union { __half2 h[2]; uint2 u; } cv;
        cv.h[0] = __floats2half2_rn(v.x, v.y);
        cv.h[1] = __floats2half2_rn(v.z, v.w);
        W1o[i] = cv.u;
        v = W24[i];
        cv.h[0] = __floats2half2_rn(v.x, v.y);
        cv.h[1] = __floats2half2_rn(v.z, v.w);
        W2o[i] = cv.u;
    }

    __shared__ int s_or;
    if (tid == 0) s_or = 0;
    __syncthreads();
    {
        const int* w = (const int*)ei;
        int cnt = (E < 2048) ? E : 2048;
        int acc = 0;
        for (int i = tid; i < cnt; i += 256) acc |= w[2 * i + 1];
        atomicOr(&s_or, acc);
    }
    __syncthreads();
    int is64 = (s_or == 0) ? 1 : 0;

    grid_barrier(PBLK);

    for (int i = gt; i < E; i += gstep) {
        int s, d;
        if (is64) {
            s = (int)((const long long*)ei)[i];
            d = (int)((const long long*)ei)[E + i];
        } else {
            s = ((const int*)ei)[i];
            d = ((const int*)ei)[E + i];
        }
        g_src[i] = s;
        g_dst[i] = d;
        atomicAdd(&g_deg[d], 1);
    }
    for (int i = gt; i < n; i += gstep)
        g_batch[i] = is64 ? (int)((const long long*)batch)[i] : ((const int*)batch)[i];
}

// K2 (persistent, 4 blocks/SM): degree scan then CSR fill.
__global__ void __launch_bounds__(256, 4) scan_fill_kernel(int n, int E) {
    __shared__ int sS[256];
    __shared__ int sS2[256];
    int tid = threadIdx.x, b = blockIdx.x;
    int C = (n + PBLK - 1) / PBLK;          // nodes per block (85)
    int ept = (C + 255) / 256;              // 1
    int nb1 = min(n, (b + 1) * C);
    int t0 = b * C + tid * ept;

    int s = 0;
    for (int i = 0; i < ept; i++) {
        int idx = t0 + i;
        if (idx < nb1) s += g_deg[idx];
    }
    sS[tid] = s;
    __syncthreads();
    for (int off = 1; off < 256; off <<= 1) {
        int v = (tid >= off) ? sS[tid - off] : 0;
        __syncthreads();
        sS[tid] += v;
        __syncthreads();
    }
    int excl = sS[tid] - s;
    if (tid == 255) g_bsum[b] = sS[255];

    grid_barrier(PBLK);

    // parallel prefix of bsum[0..b): strided partials + block tree-reduce
    {
        int part = 0;
        for (int i = tid; i < b; i += 256) part += g_bsum[i];
        sS2[tid] = part;
        __syncthreads();
        for (int off = 128; off > 0; off >>= 1) {
            if (tid < off) sS2[tid] += sS2[tid + off];
            __syncthreads();
        }
    }
    int base = sS2[0] + excl;
    for (int i = 0; i < ept; i++) {
        int idx = t0 + i;
        if (idx < nb1) {
            g_rowstart[idx] = base;
            g_cursor[idx]   = base;
            base += g_deg[idx];
        }
    }

    grid_barrier(PBLK);

    for (int e = b * 256 + tid; e < E; e += PBLK * 256) {
        int slot = atomicAdd(&g_cursor[g_dst[e]], 1);
        g_csr[slot] = g_src[e];
    }
}

// K3/K5: HMMA node GEMM. CTA = 128 rows x 128 cols x K=128, 8 warps.
// layer==0: stages from fp32 x (converts inline). layer==1: stages from g_x16.
__global__ void __launch_bounds__(256) hmma_gemm(const float* __restrict__ x,
                                                 const float* __restrict__ att,
                                                 int layer, int n) {
    extern __shared__ __half smem[];
    __half* sA = smem;                        // 128 x SA_LD
    __half* sB = smem + 128 * SA_LD;          // 128 x SA_LD (W: [k][n])
    __shared__ __align__(16) float sAtt[NC];
    __shared__ __align__(16) float sW[NC];

    int t = threadIdx.x;
    int row0 = blockIdx.x * 128;
    const __half* W16 = (layer == 0) ? g_w16a : g_w16b;
    const float* wdst = (layer == 0) ? g_wdst1 : g_wdst2;
    if (t < NC) sAtt[t] = att[t];
    else        sW[t - NC] = wdst[t - NC];

    const float4* X4 = (const float4*)x;
    #pragma unroll
    for (int i = 0; i < 8; i++) {
        int j = i * 256 + t;            // 0..2047 chunks of 8 halves
        int r = j >> 4, c8 = j & 15;
        int gr = row0 + r;
        uint4 v = make_uint4(0u, 0u, 0u, 0u);
        if (gr < n) {
            if (layer == 0) {
                float4 v0 = X4[(size_t)gr * 32 + c8 * 2];
                float4 v1 = X4[(size_t)gr * 32 + c8 * 2 + 1];
                union { __half2 h[4]; uint4 u; } cv;
                cv.h[0] = __floats2half2_rn(v0.x, v0.y);
                cv.h[1] = __floats2half2_rn(v0.z, v0.w);
                cv.h[2] = __floats2half2_rn(v1.x, v1.y);
                cv.h[3] = __floats2half2_rn(v1.z, v1.w);
                v = cv.u;
            } else {
                v = *(const uint4*)&g_x16[(size_t)gr * NC + c8 * 8];
            }
        }
        *(uint4*)&sA[r * SA_LD + c8 * 8] = v;
        uint4 wv = *(const uint4*)&W16[r * NC + c8 * 8];
        *(uint4*)&sB[r * SA_LD + c8 * 8] = wv;
    }
    __syncthreads();

    int warp = t >> 5, lane = t & 31;
    int rbase = warp * 16;

    float acc[16][4];
    #pragma unroll
    for (int j = 0; j < 16; j++)
        { acc[j][0] = 0.f; acc[j][1] = 0.f; acc[j][2] = 0.f; acc[j][3] = 0.f; }

    int a_row = rbase + (lane & 7) + ((lane >> 3) & 1) * 8;
    int a_colsel = ((lane >> 4) & 1) * 8;
    int b_krow_in16 = (lane & 7) + ((lane >> 3) & 1) * 8;

    #pragma unroll
    for (int kk = 0; kk < 8; kk++) {
        unsigned a0, a1, a2, a3;
        {
            unsigned aaddr = (unsigned)__cvta_generic_to_shared(
                &sA[a_row * SA_LD + kk * 16 + a_colsel]);
            asm volatile("ldmatrix.sync.aligned.m8n8.x4.shared.b16 {%0,%1,%2,%3}, [%4];"
                         : "=r"(a0), "=r"(a1), "=r"(a2), "=r"(a3) : "r"(aaddr));
        }
        #pragma unroll
        for (int j = 0; j < 16; j++) {
            unsigned b0, b1;
            unsigned baddr = (unsigned)__cvta_generic_to_shared(
                &sB[(kk * 16 + b_krow_in16) * SA_LD + j * 8]);
            asm volatile("ldmatrix.sync.aligned.m8n8.x2.trans.shared.b16 {%0,%1}, [%2];"
                         : "=r"(b0), "=r"(b1) : "r"(baddr));
            asm volatile(
                "mma.sync.aligned.m16n8k16.row.col.f32.f16.f16.f32 "
                "{%0,%1,%2,%3}, {%4,%5,%6,%7}, {%8,%9}, {%0,%1,%2,%3};"
                : "+f"(acc[j][0]), "+f"(acc[j][1]), "+f"(acc[j][2]), "+f"(acc[j][3])
                : "r"(a0), "r"(a1), "r"(a2), "r"(a3), "r"(b0), "r"(b1));
        }
    }

    int rL = row0 + rbase + (lane >> 2);
    int rH = rL + 8;
    int colq = (lane & 3) * 2;
    float paL = 0.f, paH = 0.f;
    #pragma unroll
    for (int j = 0; j < 16; j++) {
        float2 av = *(const float2*)&sAtt[j * 8 + colq];
        paL += acc[j][0] * av.x + acc[j][1] * av.y;
        paH += acc[j][2] * av.x + acc[j][3] * av.y;
        if (rL < n)
            *(__half2*)&g_h16[(size_t)rL * NC + j * 8 + colq] =
                __floats2half2_rn(acc[j][0], acc[j][1]);
        if (rH < n)
            *(__half2*)&g_h16[(size_t)rH * NC + j * 8 + colq] =
                __floats2half2_rn(acc[j][2], acc[j][3]);
    }
    paL += __shfl_xor_sync(0xffffffffu, paL, 1);
    paL += __shfl_xor_sync(0xffffffffu, paL, 2);
    paH += __shfl_xor_sync(0xffffffffu, paH, 1);
    paH += __shfl_xor_sync(0xffffffffu, paH, 2);
    if ((lane & 3) == 0) {
        if (rL < n) g_asrc[rL] = paL;
        if (rH < n) g_asrc[rH] = paH;
    }

    for (int r = 0; r < 16; r++) {
        int gr = row0 + rbase + r;
        uint2 raw = *(const uint2*)&sA[(rbase + r) * SA_LD + lane * 4];
        float2 f0 = __half22float2(*(__half2*)&raw.x);
        float2 f1 = __half22float2(*(__half2*)&raw.y);
        const float4 wv = *(const float4*)&sW[lane * 4];
        float pd = f0.x * wv.x + f0.y * wv.y + f1.x * wv.z + f1.y * wv.w;
        #pragma unroll
        for (int o = 16; o > 0; o >>= 1) pd += __shfl_xor_sync(0xffffffffu, pd, o);
        if (lane == 0 && gr < n) g_adst[gr] = pd;
    }
}

// K4/K6: fused softmax + CSR aggregation v2.
// TWO nodes per warp: 16-lane groups, each lane owns 8 features (uint4 gather).
// layer==0: writes g_x16 = fp16(relu(acc + bias1)).  layer==1: writes g_agg fp32.
__global__ void aggregate_fused(const float* __restrict__ bias1, int layer, int n) {
    int gw   = (blockIdx.x * blockDim.x + threadIdx.x) >> 5;
    int lane = threadIdx.x & 31;
    int grp  = lane >> 4;          // 0 or 1
    int gl   = lane & 15;
    int node = gw * 2 + grp;
    if (gw * 2 >= n) return;       // whole warp out of range
    bool active = (node < n);

    int start = 0, cnt = 0;
    float adst = 0.f;
    if (active) {
        start = g_rowstart[node];
        cnt   = g_deg[node];
        adst  = g_adst[node];
    }
    // both groups loop to the same bound (shfl-safe); padded lanes carry w=0
    int cnt_other = __shfl_xor_sync(0xffffffffu, cnt, 16);
    int cntmax = max(cnt, cnt_other);

    float dsum = 0.f;
    float acc[8];
    #pragma unroll
    for (int q = 0; q < 8; q++) acc[q] = 0.f;

    for (int j0 = 0; j0 < cntmax; j0 += 16) {
        int j = j0 + gl;
        int sN = 0; float w = 0.f;
        if (j < cnt) {
            sN = g_csr[start + j];
            float v = g_asrc[sN] + adst;
            v = (v >= 0.f) ? v : 0.2f * v;
            w = __expf(v);
        }
        dsum += w;
        int m = cntmax - j0; if (m > 16) m = 16;
        int k = 0;
        for (; k + 4 <= m; k += 4) {
            int   si[4]; float wi[4]; uint4 raw[4];
            #pragma unroll
            for (int q = 0; q < 4; q++) {
                si[q] = __shfl_sync(0xffffffffu, sN, k + q, 16);
                wi[q] = __shfl_sync(0xffffffffu, w, k + q, 16);
            }
            #pragma unroll
            for (int q = 0; q < 4; q++)
                raw[q] = *(const uint4*)&g_h16[(size_t)si[q] * NC + gl * 8];
            #pragma unroll
            for (int q = 0; q < 4; q++) {
                float2 f0 = __half22float2(*(__half2*)&raw[q].x);
                float2 f1 = __half22float2(*(__half2*)&raw[q].y);
                float2 f2 = __half22float2(*(__half2*)&raw[q].z);
                float2 f3 = __half22float2(*(__half2*)&raw[q].w);
                acc[0] += wi[q] * f0.x; acc[1] += wi[q] * f0.y;
                acc[2] += wi[q] * f1.x; acc[3] += wi[q] * f1.y;
                acc[4] += wi[q] * f2.x; acc[5] += wi[q] * f2.y;
                acc[6] += wi[q] * f3.x; acc[7] += wi[q] * f3.y;
            }
        }
        for (; k < m; k++) {
            int   sk = __shfl_sync(0xffffffffu, sN, k, 16);
            float wk = __shfl_sync(0xffffffffu, w, k, 16);
            uint4 raw = *(const uint4*)&g_h16[(size_t)sk * NC + gl * 8];
            float2 f0 = __half22float2(*(__half2*)&raw.x);
            float2 f1 = __half22float2(*(__half2*)&raw.y);
            float2 f2 = __half22float2(*(__half2*)&raw.z);
            float2 f3 = __half22float2(*(__half2*)&raw.w);
            acc[0] += wk * f0.x; acc[1] += wk * f0.y;
            acc[2] += wk * f1.x; acc[3] += wk * f1.y;
            acc[4] += wk * f2.x; acc[5] += wk * f2.y;
            acc[6] += wk * f3.x; acc[7] += wk * f3.y;
        }
    }

    // group-local reduce (xor offsets < 16 stay inside the group)
    #pragma unroll
    for (int o = 8; o > 0; o >>= 1) dsum += __shfl_xor_sync(0xffffffffu, dsum, o);
    float inv = 1.f / (dsum + 1e-16f);
    #pragma unroll
    for (int q = 0; q < 8; q++) acc[q] *= inv;

    if (!active) return;
    if (layer == 0) {
        float4 b0 = *(const float4*)&bias1[gl * 8];
        float4 b1 = *(const float4*)&bias1[gl * 8 + 4];
        union { __half2 h[4]; uint4 u; } cv;
        cv.h[0] = __floats2half2_rn(fmaxf(acc[0] + b0.x, 0.f), fmaxf(acc[1] + b0.y, 0.f));
        cv.h[1] = __floats2half2_rn(fmaxf(acc[2] + b0.z, 0.f), fmaxf(acc[3] + b0.w, 0.f));
        cv.h[2] = __floats2half2_rn(fmaxf(acc[4] + b1.x, 0.f), fmaxf(acc[5] + b1.y, 0.f));
        cv.h[3] = __floats2half2_rn(fmaxf(acc[6] + b1.z, 0.f), fmaxf(acc[7] + b1.w, 0.f));
        *(uint4*)&g_x16[(size_t)node * NC + gl * 8] = cv.u;
    } else {
        *(float4*)&g_agg[(size_t)node * NC + gl * 8] =
            make_float4(acc[0], acc[1], acc[2], acc[3]);
        *(float4*)&g_agg[(size_t)node * NC + gl * 8 + 4] =
            make_float4(acc[4], acc[5], acc[6], acc[7]);
    }
}

// K7: fused mean-pool + head. One block per graph (batch is SORTED).
__global__ void __launch_bounds__(NC) pool_head(
        const float* __restrict__ bias2, const float* __restrict__ Wl,
        const float* __restrict__ bl, float* __restrict__ out, int n) {
    __shared__ __align__(16) float sP[NC];
    __shared__ int sLo, sHi;
    int g = blockIdx.x, c = threadIdx.x;

    if (c == 0) {
        int lo = 0, hi = n;
        while (lo < hi) { int mid = (lo + hi) >> 1; if (g_batch[mid] < g) lo = mid + 1; else hi = mid; }
        sLo = lo;
        lo = 0; hi = n;
        while (lo < hi) { int mid = (lo + hi) >> 1; if (g_batch[mid] < g + 1) lo = mid + 1; else hi = mid; }
        sHi = lo;
    }
    __syncthreads();
    int s = sLo, e = sHi;
    float b = bias2[c];
    float acc = 0.f;
    for (int i = s; i < e; i++)
        acc += fmaxf(g_agg[(size_t)i * NC + c] + b, 0.f);
    float cntf = (float)(e - s);
    sP[c] = acc / fmaxf(cntf, 1.0f);
    __syncthreads();

    float o = bl[c];
    #pragma unroll 4
    for (int k = 0; k < NC; k++) o += sP[k] * Wl[k * NC + c];
    out[g * NC + c] = o;
}

extern "C" void kernel_launch(void* const* d_in, const int* in_sizes, int n_in,
                              void* d_out, int out_size) {
    const float* x     = (const float*)d_in[0];
    const void*  ei    = d_in[1];
    const void*  batch = d_in[2];
    const float* Wsrc1   = (const float*)d_in[3];
    const float* Wdst1   = (const float*)d_in[4];
    const float* attsrc1 = (const float*)d_in[5];
    const float* attdst1 = (const float*)d_in[6];
    const float* bias1   = (const float*)d_in[7];
    const float* Wsrc2   = (const float*)d_in[8];
    const float* Wdst2   = (const float*)d_in[9];
    const float* attsrc2 = (const float*)d_in[10];
    const float* attdst2 = (const float*)d_in[11];
    const float* bias2   = (const float*)d_in[12];
    const float* Wlin    = (const float*)d_in[13];
    const float* blin    = (const float*)d_in[14];

    int n = in_sizes[0] / NC;
    int E = in_sizes[1] / 2;

    int gemm_blocks = (n + 127) / 128;
    int agg_blocks  = (n + 15) / 16;          // 2 nodes/warp, 8 warps/block
    int gemm_smem   = 2 * 128 * SA_LD * (int)sizeof(__half);

    static int attr_set = 0;
    if (!attr_set) {
        cudaFuncSetAttribute(hmma_gemm, cudaFuncAttributeMaxDynamicSharedMemorySize,
                             gemm_smem);
        attr_set = 1;
    }

    mega_prep<<<PBLK, 256>>>(Wsrc1, Wsrc2, Wdst1, attdst1, Wdst2, attdst2,
                             ei, batch, E, n);
    scan_fill_kernel<<<PBLK, 256>>>(n, E);
    hmma_gemm<<<gemm_blocks, 256, gemm_smem>>>(x, attsrc1, 0, n);
    aggregate_fused<<<agg_blocks, 256>>>(bias1, 0, n);     // slot 4: ncu shows agg v2
    hmma_gemm<<<gemm_blocks, 256, gemm_smem>>>(x, attsrc2, 1, n);
    aggregate_fused<<<agg_blocks, 256>>>(nullptr, 1, n);
    pool_head<<<NG, NC>>>(bias2, Wlin, blin, (float*)d_out, n);
}